// round 4
// baseline (speedup 1.0000x reference)
#include <cuda_runtime.h>

// ---------------- constants ----------------
#define NN      50000
#define MAXE    2000000
#define HEADS   4
#define HID     64
#define HC      256          // HEADS*HID
#define OUTC    128

// ---------------- device scratch ----------------
__device__ float    g_proj[(size_t)NN * HC];
__device__ float    g_acc [(size_t)NN * HC];
__device__ float    g_h0  [(size_t)NN * HC];
__device__ float    g_h1  [(size_t)NN * HC];
__device__ float    g_lin [(size_t)NN * OUTC];
__device__ float    g_als [NN * HEADS];
__device__ float    g_ald [NN * HEADS];
__device__ unsigned g_mu  [NN * HEADS];
__device__ float    g_sden[NN * HEADS];
__device__ int      g_src [MAXE];
__device__ int      g_dst [MAXE];
__device__ int      g_is64;

// ---------------- helpers ----------------
__device__ __forceinline__ unsigned encf(float f) {
    unsigned u = __float_as_uint(f);
    return (u & 0x80000000u) ? ~u : (u | 0x80000000u);
}
__device__ __forceinline__ float decf(unsigned u) {
    return (u & 0x80000000u) ? __uint_as_float(u & 0x7fffffffu)
                             : __uint_as_float(~u);
}
__device__ __forceinline__ float lrelu(float v) { return v > 0.f ? v : 0.2f * v; }

__device__ __forceinline__ void red4(float* addr, float a, float b, float c, float d) {
    asm volatile("red.global.add.v4.f32 [%0], {%1,%2,%3,%4};"
                 :: "l"(addr), "f"(a), "f"(b), "f"(c), "f"(d) : "memory");
}

// ---------------- edge index normalization ----------------
__global__ void probe_kernel(const int* p32, int nchk) {
    if (blockIdx.x == 0 && threadIdx.x == 0) {
        int z = 0;
        for (int k = 0; k < nchk; k++)
            if (p32[2 * k + 1] == 0) z++;
        g_is64 = (z * 2 > nchk) ? 1 : 0;
    }
}

__global__ void convert_kernel(const void* ei, int E) {
    int e = blockIdx.x * blockDim.x + threadIdx.x;
    if (e >= E || e >= MAXE) return;
    if (g_is64) {
        const long long* p = (const long long*)ei;
        g_src[e] = (int)p[e];
        g_dst[e] = (int)p[(size_t)E + e];
    } else {
        const int* p = (const int*)ei;
        g_src[e] = p[e];
        g_dst[e] = p[E + e];
    }
}

// ---------------- GEMM: C[M,N] = A[M,K] @ B[K,N], fp32, row-major ----------------
// BM=BN=64, BK=16, 256 threads, 4x4 register microtile
__global__ void gemm64(const float* __restrict__ A, const float* __restrict__ B,
                       float* __restrict__ C, int M, int K, int Nn) {
    __shared__ float As[16][68];
    __shared__ float Bs[16][68];
    const int tid = threadIdx.x;
    const int tx = tid & 15;
    const int ty = tid >> 4;
    const int rowBase = blockIdx.y * 64;
    const int colBase = blockIdx.x * 64;

    const int aRow = tid >> 2;           // 0..63
    const int aCol = (tid & 3) * 4;      // 0,4,8,12
    const int bRow = tid >> 4;           // 0..15
    const int bCol = (tid & 15) * 4;     // 0..60

    float acc[4][4];
#pragma unroll
    for (int i = 0; i < 4; i++)
#pragma unroll
        for (int j = 0; j < 4; j++) acc[i][j] = 0.f;

    for (int k0 = 0; k0 < K; k0 += 16) {
        float4 av = make_float4(0.f, 0.f, 0.f, 0.f);
        int gr = rowBase + aRow;
        if (gr < M) av = *(const float4*)(A + (size_t)gr * K + k0 + aCol);
        As[aCol + 0][aRow] = av.x;
        As[aCol + 1][aRow] = av.y;
        As[aCol + 2][aRow] = av.z;
        As[aCol + 3][aRow] = av.w;
        float4 bv = *(const float4*)(B + (size_t)(k0 + bRow) * Nn + colBase + bCol);
        *(float4*)&Bs[bRow][bCol] = bv;
        __syncthreads();
#pragma unroll
        for (int kk = 0; kk < 16; kk++) {
            float4 a4 = *(const float4*)&As[kk][ty * 4];
            float4 b4 = *(const float4*)&Bs[kk][tx * 4];
            float a[4] = {a4.x, a4.y, a4.z, a4.w};
            float b[4] = {b4.x, b4.y, b4.z, b4.w};
#pragma unroll
            for (int i = 0; i < 4; i++)
#pragma unroll
                for (int j = 0; j < 4; j++) acc[i][j] = fmaf(a[i], b[j], acc[i][j]);
        }
        __syncthreads();
    }
#pragma unroll
    for (int i = 0; i < 4; i++) {
        int r = rowBase + ty * 4 + i;
        if (r < M) {
            float4 v = make_float4(acc[i][0], acc[i][1], acc[i][2], acc[i][3]);
            *(float4*)(C + (size_t)r * Nn + colBase + tx * 4) = v;
        }
    }
}

// ---------------- per-node attention logits ----------------
template <int H, int C>
__global__ void logits_kernel(const float* __restrict__ proj,
                              const float* __restrict__ a_s,
                              const float* __restrict__ a_d,
                              float* __restrict__ als, float* __restrict__ ald) {
    int w = (blockIdx.x * blockDim.x + threadIdx.x) >> 5;
    int lane = threadIdx.x & 31;
    if (w >= NN * H) return;
    int n = w / H, h = w % H;
    const float* p = proj + (size_t)n * H * C + h * C;
    float ss = 0.f, sd = 0.f;
#pragma unroll
    for (int c = lane; c < C; c += 32) {
        float v = p[c];
        ss = fmaf(v, a_s[h * C + c], ss);
        sd = fmaf(v, a_d[h * C + c], sd);
    }
#pragma unroll
    for (int o = 16; o > 0; o >>= 1) {
        ss += __shfl_xor_sync(0xffffffffu, ss, o);
        sd += __shfl_xor_sync(0xffffffffu, sd, o);
    }
    if (lane == 0) {
        als[n * H + h] = ss;
        ald[n * H + h] = sd;
    }
}

// ---------------- self-loop init of max ----------------
__global__ void self_init(const float* __restrict__ als, const float* __restrict__ ald,
                          unsigned* __restrict__ mu, int total) {
    int i = blockIdx.x * blockDim.x + threadIdx.x;
    if (i >= total) return;
    mu[i] = encf(lrelu(als[i] + ald[i]));
}

// ---------------- edge max pass ----------------
template <int H>
__global__ void edge_max(const int* __restrict__ src, const int* __restrict__ dst,
                         const float* __restrict__ als, const float* __restrict__ ald,
                         unsigned* __restrict__ mu, int E) {
    int e = blockIdx.x * blockDim.x + threadIdx.x;
    if (e >= E) return;
    int s = src[e], d = dst[e];
#pragma unroll
    for (int h = 0; h < H; h++) {
        float v = lrelu(als[s * H + h] + ald[d * H + h]);
        atomicMax(&mu[d * H + h], encf(v));
    }
}

// ---------------- self-loop init of accumulators ----------------
__global__ void agg_init(const float* __restrict__ proj, const float* __restrict__ als,
                         const float* __restrict__ ald, const unsigned* __restrict__ mu,
                         float* __restrict__ acc, float* __restrict__ sden,
                         int HCl, int Cshift, int H) {
    int idx = blockIdx.x * blockDim.x + threadIdx.x;
    int Q = HCl >> 2;
    if (idx >= NN * Q) return;
    int n = idx / Q;
    int c = (idx - n * Q) * 4;
    int h = c >> Cshift;
    float v = lrelu(als[n * H + h] + ald[n * H + h]);
    float w = __expf(v - decf(mu[n * H + h]));
    if ((c & ((1 << Cshift) - 1)) == 0) sden[n * H + h] = w;
    float4 p = *(const float4*)(proj + (size_t)n * HCl + c);
    float4 o = make_float4(w * p.x, w * p.y, w * p.z, w * p.w);
    *(float4*)(acc + (size_t)n * HCl + c) = o;
}

// ---------------- edge aggregation: warp per edge ----------------
// HC=256 (4 heads x 64): each lane covers 8 channels (2 x float4)
__global__ void edge_agg256(const int* __restrict__ src, const int* __restrict__ dst,
                            const float* __restrict__ proj, const float* __restrict__ als,
                            const float* __restrict__ ald, const unsigned* __restrict__ mu,
                            float* __restrict__ acc, float* __restrict__ sden, int E) {
    int w = (blockIdx.x * blockDim.x + threadIdx.x) >> 5;
    int lane = threadIdx.x & 31;
    if (w >= E) return;
    int s = src[w], d = dst[w];
    float wt = 0.f;
    if (lane < 4) {
        float v = lrelu(als[s * 4 + lane] + ald[d * 4 + lane]);
        wt = __expf(v - decf(mu[d * 4 + lane]));
        atomicAdd(&sden[d * 4 + lane], wt);
    }
    float wh = __shfl_sync(0xffffffffu, wt, lane >> 3);
    const float4* ps = (const float4*)(proj + (size_t)s * 256);
    float* pa = acc + (size_t)d * 256;
    float4 p0 = ps[lane * 2];
    float4 p1 = ps[lane * 2 + 1];
    red4(pa + lane * 8,     wh * p0.x, wh * p0.y, wh * p0.z, wh * p0.w);
    red4(pa + lane * 8 + 4, wh * p1.x, wh * p1.y, wh * p1.z, wh * p1.w);
}

// HC=128, 1 head: each lane covers 4 channels
__global__ void edge_agg128(const int* __restrict__ src, const int* __restrict__ dst,
                            const float* __restrict__ proj, const float* __restrict__ als,
                            const float* __restrict__ ald, const unsigned* __restrict__ mu,
                            float* __restrict__ acc, float* __restrict__ sden, int E) {
    int w = (blockIdx.x * blockDim.x + threadIdx.x) >> 5;
    int lane = threadIdx.x & 31;
    if (w >= E) return;
    int s = src[w], d = dst[w];
    float wt = 0.f;
    if (lane == 0) {
        float v = lrelu(als[s] + ald[d]);
        wt = __expf(v - decf(mu[d]));
        atomicAdd(&sden[d], wt);
    }
    wt = __shfl_sync(0xffffffffu, wt, 0);
    float4 p = ((const float4*)(proj + (size_t)s * 128))[lane];
    red4(acc + (size_t)d * 128 + lane * 4, wt * p.x, wt * p.y, wt * p.z, wt * p.w);
}

// ---------------- finalize: divide + bias (+ optional residual / linear path) --------
__global__ void finalize_kernel(const float* __restrict__ acc, const float* __restrict__ sden,
                                const float* __restrict__ bias, const float* __restrict__ bias2,
                                const float* __restrict__ res, const float* __restrict__ lin,
                                float* __restrict__ out, int HCl, int Cshift, int H) {
    int idx = blockIdx.x * blockDim.x + threadIdx.x;
    int Q = HCl >> 2;
    if (idx >= NN * Q) return;
    int n = idx / Q;
    int c = (idx - n * Q) * 4;
    int h = c >> Cshift;
    float inv = 1.0f / sden[n * H + h];
    float4 a = *(const float4*)(acc + (size_t)n * HCl + c);
    float4 b = *(const float4*)(bias + c);
    float4 o = make_float4(a.x * inv + b.x, a.y * inv + b.y, a.z * inv + b.z, a.w * inv + b.w);
    if (bias2) {
        float4 b2 = *(const float4*)(bias2 + c);
        o.x += b2.x; o.y += b2.y; o.z += b2.z; o.w += b2.w;
    }
    if (res) {
        float4 r = *(const float4*)(res + (size_t)n * HCl + c);
        o.x += r.x; o.y += r.y; o.z += r.z; o.w += r.w;
    }
    if (lin) {
        float4 l = *(const float4*)(lin + (size_t)n * HCl + c);
        o.x += l.x; o.y += l.y; o.z += l.z; o.w += l.w;
    }
    *(float4*)(out + (size_t)n * HCl + c) = o;
}

// ---------------- host orchestration ----------------
extern "C" void kernel_launch(void* const* d_in, const int* in_sizes, int n_in,
                              void* d_out, int out_size) {
    const float* x   = (const float*)d_in[0];
    const void*  ei  = d_in[1];
    const float* W0  = (const float*)d_in[2];
    const float* as0 = (const float*)d_in[3];
    const float* ad0 = (const float*)d_in[4];
    const float* b0  = (const float*)d_in[5];
    const float* W1  = (const float*)d_in[6];
    const float* as1 = (const float*)d_in[7];
    const float* ad1 = (const float*)d_in[8];
    const float* b1  = (const float*)d_in[9];
    const float* W2  = (const float*)d_in[10];
    const float* as2 = (const float*)d_in[11];
    const float* ad2 = (const float*)d_in[12];
    const float* b2  = (const float*)d_in[13];
    const float* Wl  = (const float*)d_in[14];
    const float* bl  = (const float*)d_in[15];
    float* out = (float*)d_out;
    const int E = in_sizes[1] / 2;

    float *p_proj, *p_acc, *p_h0, *p_h1, *p_lin, *p_als, *p_ald, *p_sden;
    unsigned* p_mu;
    int *p_src, *p_dst;
    cudaGetSymbolAddress((void**)&p_proj, g_proj);
    cudaGetSymbolAddress((void**)&p_acc,  g_acc);
    cudaGetSymbolAddress((void**)&p_h0,   g_h0);
    cudaGetSymbolAddress((void**)&p_h1,   g_h1);
    cudaGetSymbolAddress((void**)&p_lin,  g_lin);
    cudaGetSymbolAddress((void**)&p_als,  g_als);
    cudaGetSymbolAddress((void**)&p_ald,  g_ald);
    cudaGetSymbolAddress((void**)&p_sden, g_sden);
    cudaGetSymbolAddress((void**)&p_mu,   g_mu);
    cudaGetSymbolAddress((void**)&p_src,  g_src);
    cudaGetSymbolAddress((void**)&p_dst,  g_dst);

    // normalize edge index dtype (int32 vs int64) into int32 scratch
    probe_kernel<<<1, 32>>>((const int*)ei, E > 1024 ? 1024 : E);
    convert_kernel<<<(E + 255) / 256, 256>>>(ei, E);

    auto run_layer = [&](const float* inp, const float* W, const float* a_s,
                         const float* a_d, const float* bias, int H, int C,
                         const float* res, const float* lin, const float* bias2,
                         float* outp) {
        const int HCl = H * C;
        const int Cshift = (C == 64) ? 6 : 7;
        gemm64<<<dim3(HCl / 64, (NN + 63) / 64), 256>>>(inp, W, p_proj, NN, 256, HCl);
        int warps = NN * H;
        if (H == 4)
            logits_kernel<4, 64><<<(warps * 32 + 255) / 256, 256>>>(p_proj, a_s, a_d, p_als, p_ald);
        else
            logits_kernel<1, 128><<<(warps * 32 + 255) / 256, 256>>>(p_proj, a_s, a_d, p_als, p_ald);
        self_init<<<(NN * H + 255) / 256, 256>>>(p_als, p_ald, p_mu, NN * H);
        if (H == 4)
            edge_max<4><<<(E + 255) / 256, 256>>>(p_src, p_dst, p_als, p_ald, p_mu, E);
        else
            edge_max<1><<<(E + 255) / 256, 256>>>(p_src, p_dst, p_als, p_ald, p_mu, E);
        int q = NN * HCl / 4;
        agg_init<<<(q + 255) / 256, 256>>>(p_proj, p_als, p_ald, p_mu, p_acc, p_sden, HCl, Cshift, H);
        long long tthreads = (long long)E * 32;
        int blocks = (int)((tthreads + 255) / 256);
        if (H == 4)
            edge_agg256<<<blocks, 256>>>(p_src, p_dst, p_proj, p_als, p_ald, p_mu, p_acc, p_sden, E);
        else
            edge_agg128<<<blocks, 256>>>(p_src, p_dst, p_proj, p_als, p_ald, p_mu, p_acc, p_sden, E);
        finalize_kernel<<<(q + 255) / 256, 256>>>(p_acc, p_sden, bias, bias2, res, lin, outp, HCl, Cshift, H);
    };

    // layer 0: x -> h0
    run_layer(x, W0, as0, ad0, b0, 4, 64, nullptr, nullptr, nullptr, p_h0);
    // layer 1: h0 -> h1 (residual h0)
    run_layer(p_h0, W1, as1, ad1, b1, 4, 64, p_h0, nullptr, nullptr, p_h1);
    // linear skip path: lin = h1 @ Wl
    gemm64<<<dim3(OUTC / 64, (NN + 63) / 64), 256>>>(p_h1, Wl, p_lin, NN, 256, OUTC);
    // layer 2: h1 -> out (1 head, 128 ch), + lin + bl
    run_layer(p_h1, W2, as2, ad2, b2, 1, 128, nullptr, p_lin, bl, out);
}

// round 6
// speedup vs baseline: 1.2146x; 1.2146x over previous
#include <cuda_runtime.h>
#include <cuda_bf16.h>
#include <cstdint>

// ---------------- constants ----------------
#define NN      50000
#define MAXE    2000000
#define HEADS   4
#define HC      256          // HEADS*HID
#define OUTC    128
#define KDIM    256          // all GEMMs have K=256

// ---------------- device scratch ----------------
__device__ float    g_proj[(size_t)NN * HC];
__device__ float    g_acc [(size_t)NN * HC];
__device__ float    g_h0  [(size_t)NN * HC];
__device__ float    g_h1  [(size_t)NN * HC];
__device__ float    g_lin [(size_t)NN * OUTC];
__device__ float    g_als [NN * HEADS];
__device__ float    g_ald [NN * HEADS];
__device__ float    g_sden[NN * HEADS];
__device__ int      g_src [MAXE];
__device__ int      g_dst [MAXE];
__device__ int      g_is64;
// bf16 split activations (reused across layers) and transposed split weights [N,K]
__device__ __nv_bfloat16 g_ahi[(size_t)NN * KDIM];
__device__ __nv_bfloat16 g_alo[(size_t)NN * KDIM];
__device__ __nv_bfloat16 g_w0hi[KDIM * HC],   g_w0lo[KDIM * HC];
__device__ __nv_bfloat16 g_w1hi[KDIM * HC],   g_w1lo[KDIM * HC];
__device__ __nv_bfloat16 g_w2hi[KDIM * OUTC], g_w2lo[KDIM * OUTC];
__device__ __nv_bfloat16 g_wlhi[KDIM * OUTC], g_wllo[KDIM * OUTC];

// ---------------- helpers ----------------
__device__ __forceinline__ float lrelu(float v) { return v > 0.f ? v : 0.2f * v; }

__device__ __forceinline__ void red4(float* addr, float a, float b, float c, float d) {
    asm volatile("red.global.add.v4.f32 [%0], {%1,%2,%3,%4};"
                 :: "l"(addr), "f"(a), "f"(b), "f"(c), "f"(d) : "memory");
}

__device__ __forceinline__ uint32_t s2u(const void* p) {
    uint32_t a;
    asm("{ .reg .u64 t; cvta.to.shared.u64 t, %1; cvt.u32.u64 %0, t; }" : "=r"(a) : "l"(p));
    return a;
}

#define LDM4(d, addr) \
    asm volatile("ldmatrix.sync.aligned.m8n8.x4.shared.b16 {%0,%1,%2,%3}, [%4];" \
        : "=r"((d)[0]), "=r"((d)[1]), "=r"((d)[2]), "=r"((d)[3]) : "r"(addr))

#define MMA_BF16(c, a, b0, b1) \
    asm volatile("mma.sync.aligned.m16n8k16.row.col.f32.bf16.bf16.f32 " \
        "{%0,%1,%2,%3}, {%4,%5,%6,%7}, {%8,%9}, {%0,%1,%2,%3};" \
        : "+f"((c)[0]), "+f"((c)[1]), "+f"((c)[2]), "+f"((c)[3]) \
        : "r"((a)[0]), "r"((a)[1]), "r"((a)[2]), "r"((a)[3]), "r"(b0), "r"(b1))

// ---------------- edge index normalization ----------------
__global__ void probe_kernel(const int* p32, int nchk) {
    if (blockIdx.x == 0 && threadIdx.x == 0) {
        int z = 0;
        for (int k = 0; k < nchk; k++)
            if (p32[2 * k + 1] == 0) z++;
        g_is64 = (z * 2 > nchk) ? 1 : 0;
    }
}

__global__ void convert_kernel(const void* ei, int E) {
    int e = blockIdx.x * blockDim.x + threadIdx.x;
    if (e >= E || e >= MAXE) return;
    if (g_is64) {
        const long long* p = (const long long*)ei;
        g_src[e] = (int)p[e];
        g_dst[e] = (int)p[(size_t)E + e];
    } else {
        const int* p = (const int*)ei;
        g_src[e] = p[e];
        g_dst[e] = p[E + e];
    }
}

// ---------------- bf16 hi/lo split of activations ----------------
__global__ void split_act(const float* __restrict__ in, __nv_bfloat16* __restrict__ hi,
                          __nv_bfloat16* __restrict__ lo, int total4) {
    int i = blockIdx.x * blockDim.x + threadIdx.x;
    if (i >= total4) return;
    float4 v = ((const float4*)in)[i];
    float vv[4] = {v.x, v.y, v.z, v.w};
    __nv_bfloat16 h[4], l[4];
#pragma unroll
    for (int j = 0; j < 4; j++) {
        h[j] = __float2bfloat16(vv[j]);
        l[j] = __float2bfloat16(vv[j] - __bfloat162float(h[j]));
    }
    ((__nv_bfloat162*)hi)[2 * i]     = __nv_bfloat162(h[0], h[1]);
    ((__nv_bfloat162*)hi)[2 * i + 1] = __nv_bfloat162(h[2], h[3]);
    ((__nv_bfloat162*)lo)[2 * i]     = __nv_bfloat162(l[0], l[1]);
    ((__nv_bfloat162*)lo)[2 * i + 1] = __nv_bfloat162(l[2], l[3]);
}

// ---------------- weight transpose + split: W[K,N] -> Wt[N,K] hi/lo ----------------
__global__ void wsplit(const float* __restrict__ W, int Nn,
                       __nv_bfloat16* __restrict__ hi, __nv_bfloat16* __restrict__ lo) {
    int idx = blockIdx.x * blockDim.x + threadIdx.x;   // n*256 + k
    if (idx >= Nn * KDIM) return;
    int n = idx >> 8, k = idx & 255;
    float v = W[(size_t)k * Nn + n];
    __nv_bfloat16 h = __float2bfloat16(v);
    hi[idx] = h;
    lo[idx] = __float2bfloat16(v - __bfloat162float(h));
}

// ---------------- HMMA split-bf16 GEMM ----------------
// C[M, Nn] = A[M,256] @ Wt[Nn,256]^T, fp32 accum via hi*hi + hi*lo + lo*hi.
// Block tile 128x64, 256 threads (8 warps, warp tile 32x32).
// SMEM stride 56 bf16 (112B): ldmatrix row offsets mod 128B are all distinct.
__global__ void __launch_bounds__(256, 2) gemm_mma(
    const __nv_bfloat16* __restrict__ Ahi, const __nv_bfloat16* __restrict__ Alo,
    const __nv_bfloat16* __restrict__ Bhi, const __nv_bfloat16* __restrict__ Blo,
    float* __restrict__ C, int M, int Nn)
{
    __shared__ __align__(16) char smem[43008];
    constexpr int A_HI = 0;
    constexpr int A_LO = 14336;            // 128*112
    constexpr int B_HI = 28672;
    constexpr int B_LO = 35840;            // + 64*112

    const int tid  = threadIdx.x;
    const int lane = tid & 31;
    const int wid  = tid >> 5;
    const int warpRow = wid & 3;           // 4 x 32 rows  = 128
    const int warpCol = wid >> 2;          // 2 x 32 cols  = 64
    const int rowBase = blockIdx.x * 128;
    const int colBase = blockIdx.y * 64;

    float acc[2][4][4];
#pragma unroll
    for (int i = 0; i < 2; i++)
#pragma unroll
        for (int j = 0; j < 4; j++)
#pragma unroll
            for (int q = 0; q < 4; q++) acc[i][j][q] = 0.f;

    const uint32_t sb = s2u(smem);
    // ldmatrix base addresses (per-thread, fixed; add kk*32 bytes per k16 step)
    uint32_t aAdrH[2], aAdrL[2];
#pragma unroll
    for (int m16 = 0; m16 < 2; m16++) {
        uint32_t r = warpRow * 32 + m16 * 16 + (lane & 15);
        uint32_t cb = ((lane >> 4) * 8) * 2;
        aAdrH[m16] = sb + A_HI + r * 112 + cb;
        aAdrL[m16] = sb + A_LO + r * 112 + cb;
    }
    uint32_t bAdrH[2], bAdrL[2];
#pragma unroll
    for (int nbp = 0; nbp < 2; nbp++) {
        uint32_t r = warpCol * 32 + nbp * 16 + ((lane >> 4) << 3) + (lane & 7);
        uint32_t cb = (((lane >> 3) & 1) * 8) * 2;
        bAdrH[nbp] = sb + B_HI + r * 112 + cb;
        bAdrL[nbp] = sb + B_LO + r * 112 + cb;
    }

    for (int k0 = 0; k0 < KDIM; k0 += 32) {
        // ---- stage A tile (128 x 32 bf16, hi+lo), guarded ----
#pragma unroll
        for (int it = 0; it < 2; it++) {
            int i = tid + it * 256;               // 0..511
            int r = i >> 2, c = (i & 3) * 8;
            uint4 vh = make_uint4(0, 0, 0, 0), vl = vh;
            int gr = rowBase + r;
            if (gr < M) {
                size_t g = (size_t)gr * KDIM + k0 + c;
                vh = *(const uint4*)(Ahi + g);
                vl = *(const uint4*)(Alo + g);
            }
            *(uint4*)(smem + A_HI + r * 112 + c * 2) = vh;
            *(uint4*)(smem + A_LO + r * 112 + c * 2) = vl;
        }
        // ---- stage B tile (64 x 32 bf16, hi+lo) ----
        {
            int r = tid >> 2, c = (tid & 3) * 8;
            size_t g = (size_t)(colBase + r) * KDIM + k0 + c;
            *(uint4*)(smem + B_HI + r * 112 + c * 2) = *(const uint4*)(Bhi + g);
            *(uint4*)(smem + B_LO + r * 112 + c * 2) = *(const uint4*)(Blo + g);
        }
        __syncthreads();

#pragma unroll
        for (int kk = 0; kk < 2; kk++) {
            const uint32_t kb = kk * 32;          // 16 bf16 = 32 bytes
            uint32_t ah[2][4], al[2][4], bh[2][4], bl[2][4];
            LDM4(ah[0], aAdrH[0] + kb);
            LDM4(ah[1], aAdrH[1] + kb);
            LDM4(al[0], aAdrL[0] + kb);
            LDM4(al[1], aAdrL[1] + kb);
            LDM4(bh[0], bAdrH[0] + kb);
            LDM4(bh[1], bAdrH[1] + kb);
            LDM4(bl[0], bAdrL[0] + kb);
            LDM4(bl[1], bAdrL[1] + kb);
#pragma unroll
            for (int m16 = 0; m16 < 2; m16++) {
#pragma unroll
                for (int nb = 0; nb < 4; nb++) {
                    const int p = nb >> 1, q = (nb & 1) * 2;
                    MMA_BF16(acc[m16][nb], ah[m16], bh[p][q], bh[p][q + 1]);
                    MMA_BF16(acc[m16][nb], ah[m16], bl[p][q], bl[p][q + 1]);
                    MMA_BF16(acc[m16][nb], al[m16], bh[p][q], bh[p][q + 1]);
                }
            }
        }
        __syncthreads();
    }

    // ---- epilogue ----
#pragma unroll
    for (int m16 = 0; m16 < 2; m16++) {
        int r0 = rowBase + warpRow * 32 + m16 * 16 + (lane >> 2);
#pragma unroll
        for (int nb = 0; nb < 4; nb++) {
            int col = colBase + warpCol * 32 + nb * 8 + (lane & 3) * 2;
            if (r0 < M)
                *(float2*)(C + (size_t)r0 * Nn + col) =
                    make_float2(acc[m16][nb][0], acc[m16][nb][1]);
            if (r0 + 8 < M)
                *(float2*)(C + (size_t)(r0 + 8) * Nn + col) =
                    make_float2(acc[m16][nb][2], acc[m16][nb][3]);
        }
    }
}

// ---------------- per-node attention logits ----------------
template <int H, int C>
__global__ void logits_kernel(const float* __restrict__ proj,
                              const float* __restrict__ a_s,
                              const float* __restrict__ a_d,
                              float* __restrict__ als, float* __restrict__ ald) {
    int w = (blockIdx.x * blockDim.x + threadIdx.x) >> 5;
    int lane = threadIdx.x & 31;
    if (w >= NN * H) return;
    int n = w / H, h = w % H;
    const float* p = proj + (size_t)n * H * C + h * C;
    float ss = 0.f, sd = 0.f;
#pragma unroll
    for (int c = lane; c < C; c += 32) {
        float v = p[c];
        ss = fmaf(v, a_s[h * C + c], ss);
        sd = fmaf(v, a_d[h * C + c], sd);
    }
#pragma unroll
    for (int o = 16; o > 0; o >>= 1) {
        ss += __shfl_xor_sync(0xffffffffu, ss, o);
        sd += __shfl_xor_sync(0xffffffffu, sd, o);
    }
    if (lane == 0) {
        als[n * H + h] = ss;
        ald[n * H + h] = sd;
    }
}

// ---------------- self-loop init of accumulators (no max pass: exp directly) --------
__global__ void agg_init(const float* __restrict__ proj, const float* __restrict__ als,
                         const float* __restrict__ ald,
                         float* __restrict__ acc, float* __restrict__ sden,
                         int HCl, int Cshift, int H) {
    int idx = blockIdx.x * blockDim.x + threadIdx.x;
    int Q = HCl >> 2;
    if (idx >= NN * Q) return;
    int n = idx / Q;
    int c = (idx - n * Q) * 4;
    int h = c >> Cshift;
    float w = __expf(lrelu(als[n * H + h] + ald[n * H + h]));
    if ((c & ((1 << Cshift) - 1)) == 0) sden[n * H + h] = w;
    float4 p = *(const float4*)(proj + (size_t)n * HCl + c);
    *(float4*)(acc + (size_t)n * HCl + c) = make_float4(w * p.x, w * p.y, w * p.z, w * p.w);
}

// ---------------- edge aggregation: warp per edge ----------------
__global__ void edge_agg256(const int* __restrict__ src, const int* __restrict__ dst,
                            const float* __restrict__ proj, const float* __restrict__ als,
                            const float* __restrict__ ald,
                            float* __restrict__ acc, float* __restrict__ sden, int E) {
    int w = (blockIdx.x * blockDim.x + threadIdx.x) >> 5;
    int lane = threadIdx.x & 31;
    if (w >= E) return;
    int s = src[w], d = dst[w];
    float wt = 0.f;
    if (lane < 4) {
        wt = __expf(lrelu(als[s * 4 + lane] + ald[d * 4 + lane]));
        atomicAdd(&sden[d * 4 + lane], wt);
    }
    float wh = __shfl_sync(0xffffffffu, wt, lane >> 3);
    const float4* ps = (const float4*)(proj + (size_t)s * 256);
    float* pa = acc + (size_t)d * 256;
    float4 p0 = ps[lane * 2];
    float4 p1 = ps[lane * 2 + 1];
    red4(pa + lane * 8,     wh * p0.x, wh * p0.y, wh * p0.z, wh * p0.w);
    red4(pa + lane * 8 + 4, wh * p1.x, wh * p1.y, wh * p1.z, wh * p1.w);
}

__global__ void edge_agg128(const int* __restrict__ src, const int* __restrict__ dst,
                            const float* __restrict__ proj, const float* __restrict__ als,
                            const float* __restrict__ ald,
                            float* __restrict__ acc, float* __restrict__ sden, int E) {
    int w = (blockIdx.x * blockDim.x + threadIdx.x) >> 5;
    int lane = threadIdx.x & 31;
    if (w >= E) return;
    int s = src[w], d = dst[w];
    float wt = 0.f;
    if (lane == 0) {
        wt = __expf(lrelu(als[s] + ald[d]));
        atomicAdd(&sden[d], wt);
    }
    wt = __shfl_sync(0xffffffffu, wt, 0);
    float4 p = ((const float4*)(proj + (size_t)s * 128))[lane];
    red4(acc + (size_t)d * 128 + lane * 4, wt * p.x, wt * p.y, wt * p.z, wt * p.w);
}

// ---------------- finalize: divide + bias (+ optional residual / linear path) --------
__global__ void finalize_kernel(const float* __restrict__ acc, const float* __restrict__ sden,
                                const float* __restrict__ bias, const float* __restrict__ bias2,
                                const float* __restrict__ res, const float* __restrict__ lin,
                                float* __restrict__ out, int HCl, int Cshift, int H) {
    int idx = blockIdx.x * blockDim.x + threadIdx.x;
    int Q = HCl >> 2;
    if (idx >= NN * Q) return;
    int n = idx / Q;
    int c = (idx - n * Q) * 4;
    int h = c >> Cshift;
    float inv = 1.0f / sden[n * H + h];
    float4 a = *(const float4*)(acc + (size_t)n * HCl + c);
    float4 b = *(const float4*)(bias + c);
    float4 o = make_float4(a.x * inv + b.x, a.y * inv + b.y, a.z * inv + b.z, a.w * inv + b.w);
    if (bias2) {
        float4 b2 = *(const float4*)(bias2 + c);
        o.x += b2.x; o.y += b2.y; o.z += b2.z; o.w += b2.w;
    }
    if (res) {
        float4 r = *(const float4*)(res + (size_t)n * HCl + c);
        o.x += r.x; o.y += r.y; o.z += r.z; o.w += r.w;
    }
    if (lin) {
        float4 l = *(const float4*)(lin + (size_t)n * HCl + c);
        o.x += l.x; o.y += l.y; o.z += l.z; o.w += l.w;
    }
    *(float4*)(out + (size_t)n * HCl + c) = o;
}

// ---------------- host orchestration ----------------
extern "C" void kernel_launch(void* const* d_in, const int* in_sizes, int n_in,
                              void* d_out, int out_size) {
    const float* x   = (const float*)d_in[0];
    const void*  ei  = d_in[1];
    const float* W0  = (const float*)d_in[2];
    const float* as0 = (const float*)d_in[3];
    const float* ad0 = (const float*)d_in[4];
    const float* b0  = (const float*)d_in[5];
    const float* W1  = (const float*)d_in[6];
    const float* as1 = (const float*)d_in[7];
    const float* ad1 = (const float*)d_in[8];
    const float* b1  = (const float*)d_in[9];
    const float* W2  = (const float*)d_in[10];
    const float* as2 = (const float*)d_in[11];
    const float* ad2 = (const float*)d_in[12];
    const float* b2  = (const float*)d_in[13];
    const float* Wl  = (const float*)d_in[14];
    const float* bl  = (const float*)d_in[15];
    float* out = (float*)d_out;
    const int E = in_sizes[1] / 2;

    float *p_proj, *p_acc, *p_h0, *p_h1, *p_lin, *p_als, *p_ald, *p_sden;
    int *p_src, *p_dst;
    __nv_bfloat16 *p_ahi, *p_alo, *p_w0hi, *p_w0lo, *p_w1hi, *p_w1lo,
                  *p_w2hi, *p_w2lo, *p_wlhi, *p_wllo;
    cudaGetSymbolAddress((void**)&p_proj, g_proj);
    cudaGetSymbolAddress((void**)&p_acc,  g_acc);
    cudaGetSymbolAddress((void**)&p_h0,   g_h0);
    cudaGetSymbolAddress((void**)&p_h1,   g_h1);
    cudaGetSymbolAddress((void**)&p_lin,  g_lin);
    cudaGetSymbolAddress((void**)&p_als,  g_als);
    cudaGetSymbolAddress((void**)&p_ald,  g_ald);
    cudaGetSymbolAddress((void**)&p_sden, g_sden);
    cudaGetSymbolAddress((void**)&p_src,  g_src);
    cudaGetSymbolAddress((void**)&p_dst,  g_dst);
    cudaGetSymbolAddress((void**)&p_ahi,  g_ahi);
    cudaGetSymbolAddress((void**)&p_alo,  g_alo);
    cudaGetSymbolAddress((void**)&p_w0hi, g_w0hi);
    cudaGetSymbolAddress((void**)&p_w0lo, g_w0lo);
    cudaGetSymbolAddress((void**)&p_w1hi, g_w1hi);
    cudaGetSymbolAddress((void**)&p_w1lo, g_w1lo);
    cudaGetSymbolAddress((void**)&p_w2hi, g_w2hi);
    cudaGetSymbolAddress((void**)&p_w2lo, g_w2lo);
    cudaGetSymbolAddress((void**)&p_wlhi, g_wlhi);
    cudaGetSymbolAddress((void**)&p_wllo, g_wllo);

    // normalize edge index dtype (int32 vs int64) into int32 scratch
    probe_kernel<<<1, 32>>>((const int*)ei, E > 1024 ? 1024 : E);
    convert_kernel<<<(E + 255) / 256, 256>>>(ei, E);

    // weight prep: transpose + bf16 split
    wsplit<<<(HC * KDIM + 255) / 256, 256>>>(W0, HC, p_w0hi, p_w0lo);
    wsplit<<<(HC * KDIM + 255) / 256, 256>>>(W1, HC, p_w1hi, p_w1lo);
    wsplit<<<(OUTC * KDIM + 255) / 256, 256>>>(W2, OUTC, p_w2hi, p_w2lo);
    wsplit<<<(OUTC * KDIM + 255) / 256, 256>>>(Wl, OUTC, p_wlhi, p_wllo);

    const int GEMM_BX = (NN + 127) / 128;
    const int total4 = NN * KDIM / 4;
    const long long tthreads = (long long)E * 32;
    const int agg_blocks = (int)((tthreads + 255) / 256);

    auto run_edges = [&](const float* bias, const float* bias2, const float* res,
                         const float* lin, int H, int C, float* outp) {
        const int HCl = H * C;
        const int Cshift = (C == 64) ? 6 : 7;
        const int q = NN * HCl / 4;
        agg_init<<<(q + 255) / 256, 256>>>(p_proj, p_als, p_ald, p_acc, p_sden, HCl, Cshift, H);
        if (H == 4)
            edge_agg256<<<agg_blocks, 256>>>(p_src, p_dst, p_proj, p_als, p_ald, p_acc, p_sden, E);
        else
            edge_agg128<<<agg_blocks, 256>>>(p_src, p_dst, p_proj, p_als, p_ald, p_acc, p_sden, E);
        finalize_kernel<<<(q + 255) / 256, 256>>>(p_acc, p_sden, bias, bias2, res, lin,
                                                  outp, HCl, Cshift, H);
    };

    // ---- layer 0: x -> h0 ----
    split_act<<<(total4 + 255) / 256, 256>>>(x, p_ahi, p_alo, total4);
    gemm_mma<<<dim3(GEMM_BX, HC / 64), 256>>>(p_ahi, p_alo, p_w0hi, p_w0lo, p_proj, NN, HC);
    logits_kernel<4, 64><<<(NN * 4 * 32 + 255) / 256, 256>>>(p_proj, as0, ad0, p_als, p_ald);
    run_edges(b0, nullptr, nullptr, nullptr, 4, 64, p_h0);

    // ---- layer 1: h0 -> h1 (residual h0) ----
    split_act<<<(total4 + 255) / 256, 256>>>(p_h0, p_ahi, p_alo, total4);
    gemm_mma<<<dim3(GEMM_BX, HC / 64), 256>>>(p_ahi, p_alo, p_w1hi, p_w1lo, p_proj, NN, HC);
    logits_kernel<4, 64><<<(NN * 4 * 32 + 255) / 256, 256>>>(p_proj, as1, ad1, p_als, p_ald);
    run_edges(b1, nullptr, p_h0, nullptr, 4, 64, p_h1);

    // ---- layer 2: h1 -> out (1 head, 128 ch), + h1@Wl + bl ----
    split_act<<<(total4 + 255) / 256, 256>>>(p_h1, p_ahi, p_alo, total4);
    gemm_mma<<<dim3(GEMM_BX, OUTC / 64), 256>>>(p_ahi, p_alo, p_wlhi, p_wllo, p_lin, NN, OUTC);
    gemm_mma<<<dim3(GEMM_BX, OUTC / 64), 256>>>(p_ahi, p_alo, p_w2hi, p_w2lo, p_proj, NN, OUTC);
    logits_kernel<1, 128><<<(NN * 32 + 255) / 256, 256>>>(p_proj, as2, ad2, p_als, p_ald);
    run_edges(b2, bl, nullptr, p_lin, 1, 128, out);
}

// round 7
// speedup vs baseline: 2.3625x; 1.9451x over previous
#include <cuda_runtime.h>
#include <cuda_bf16.h>
#include <cstdint>

// ---------------- constants ----------------
#define NN      50000
#define MAXE    2000000
#define HEADS   4
#define HC      256          // HEADS*HID
#define OUTC    128
#define KDIM    256          // all GEMMs have K=256

// ---------------- device scratch ----------------
__device__ float    g_proj[(size_t)NN * HC];
__device__ float    g_h0  [(size_t)NN * HC];
__device__ float    g_als [NN * HEADS];
__device__ float    g_ald [NN * HEADS];
__device__ int      g_src [MAXE];
__device__ int      g_dst [MAXE];
__device__ int      g_ssrc[MAXE];
__device__ int      g_cnt [NN];
__device__ int      g_cursor[NN];
__device__ int      g_rowptr[NN + 1];
__device__ int      g_is64;
// bf16 split activations (reused across layers) and transposed split weights [N,K]
__device__ __nv_bfloat16 g_ahi[(size_t)NN * KDIM];
__device__ __nv_bfloat16 g_alo[(size_t)NN * KDIM];
__device__ __nv_bfloat16 g_w0hi[KDIM * HC],  g_w0lo[KDIM * HC];
__device__ __nv_bfloat16 g_w1hi[KDIM * HC],  g_w1lo[KDIM * HC];
__device__ __nv_bfloat16 g_wchi[KDIM * 256], g_wclo[KDIM * 256];  // [W2 | Wl] combined

// ---------------- helpers ----------------
__device__ __forceinline__ float lrelu(float v) { return v > 0.f ? v : 0.2f * v; }

__device__ __forceinline__ uint32_t s2u(const void* p) {
    uint32_t a;
    asm("{ .reg .u64 t; cvta.to.shared.u64 t, %1; cvt.u32.u64 %0, t; }" : "=r"(a) : "l"(p));
    return a;
}

#define LDM4(d, addr) \
    asm volatile("ldmatrix.sync.aligned.m8n8.x4.shared.b16 {%0,%1,%2,%3}, [%4];" \
        : "=r"((d)[0]), "=r"((d)[1]), "=r"((d)[2]), "=r"((d)[3]) : "r"(addr))

#define MMA_BF16(c, a, b0, b1) \
    asm volatile("mma.sync.aligned.m16n8k16.row.col.f32.bf16.bf16.f32 " \
        "{%0,%1,%2,%3}, {%4,%5,%6,%7}, {%8,%9}, {%0,%1,%2,%3};" \
        : "+f"((c)[0]), "+f"((c)[1]), "+f"((c)[2]), "+f"((c)[3]) \
        : "r"((a)[0]), "r"((a)[1]), "r"((a)[2]), "r"((a)[3]), "r"(b0), "r"(b1))

// ---------------- edge index prep: dtype normalize + dst histogram ----------------
__global__ void probe_kernel(const int* p32, int nchk) {
    if (blockIdx.x == 0 && threadIdx.x == 0) {
        int z = 0;
        for (int k = 0; k < nchk; k++)
            if (p32[2 * k + 1] == 0) z++;
        g_is64 = (z * 2 > nchk) ? 1 : 0;
    }
}

__global__ void zero_cnt() {
    int i = blockIdx.x * blockDim.x + threadIdx.x;
    if (i < NN) g_cnt[i] = 0;
}

__global__ void convert_hist(const void* ei, int E) {
    int e = blockIdx.x * blockDim.x + threadIdx.x;
    if (e >= E || e >= MAXE) return;
    int s, d;
    if (g_is64) {
        const long long* p = (const long long*)ei;
        s = (int)p[e];
        d = (int)p[(size_t)E + e];
    } else {
        const int* p = (const int*)ei;
        s = p[e];
        d = p[E + e];
    }
    g_src[e] = s;
    g_dst[e] = d;
    atomicAdd(&g_cnt[d], 1);
}

// single-block exclusive scan over g_cnt -> g_rowptr / g_cursor
__global__ void scan_kernel() {
    __shared__ int sm[1024];
    __shared__ int carry;
    if (threadIdx.x == 0) carry = 0;
    __syncthreads();
    for (int base = 0; base < NN; base += 1024) {
        int i = base + (int)threadIdx.x;
        int v = (i < NN) ? g_cnt[i] : 0;
        sm[threadIdx.x] = v;
        __syncthreads();
#pragma unroll
        for (int off = 1; off < 1024; off <<= 1) {
            int t = (threadIdx.x >= (unsigned)off) ? sm[threadIdx.x - off] : 0;
            __syncthreads();
            sm[threadIdx.x] += t;
            __syncthreads();
        }
        int excl = sm[threadIdx.x] - v + carry;
        if (i < NN) { g_rowptr[i] = excl; g_cursor[i] = excl; }
        __syncthreads();
        if (threadIdx.x == 1023) carry += sm[1023];
        __syncthreads();
    }
    if (threadIdx.x == 0) g_rowptr[NN] = carry;
}

__global__ void scatter_kernel(int E) {
    int e = blockIdx.x * blockDim.x + threadIdx.x;
    if (e >= E || e >= MAXE) return;
    int pos = atomicAdd(&g_cursor[g_dst[e]], 1);
    g_ssrc[pos] = g_src[e];
}

// ---------------- bf16 hi/lo split (layer-0 input only) ----------------
__global__ void split_act(const float* __restrict__ in, __nv_bfloat16* __restrict__ hi,
                          __nv_bfloat16* __restrict__ lo, int total4) {
    int i = blockIdx.x * blockDim.x + threadIdx.x;
    if (i >= total4) return;
    float4 v = ((const float4*)in)[i];
    float vv[4] = {v.x, v.y, v.z, v.w};
    __nv_bfloat16 h[4], l[4];
#pragma unroll
    for (int j = 0; j < 4; j++) {
        h[j] = __float2bfloat16(vv[j]);
        l[j] = __float2bfloat16(vv[j] - __bfloat162float(h[j]));
    }
    ((__nv_bfloat162*)hi)[2 * i]     = __nv_bfloat162(h[0], h[1]);
    ((__nv_bfloat162*)hi)[2 * i + 1] = __nv_bfloat162(h[2], h[3]);
    ((__nv_bfloat162*)lo)[2 * i]     = __nv_bfloat162(l[0], l[1]);
    ((__nv_bfloat162*)lo)[2 * i + 1] = __nv_bfloat162(l[2], l[3]);
}

// ---------------- weight transpose + split: W[K,N] -> Wt[N,K] hi/lo ----------------
// Wt rows written with row stride KDIM into (hi + rowOfs*KDIM).
__global__ void wsplit(const float* __restrict__ W, int Nn,
                       __nv_bfloat16* __restrict__ hi, __nv_bfloat16* __restrict__ lo) {
    int idx = blockIdx.x * blockDim.x + threadIdx.x;   // n*256 + k
    if (idx >= Nn * KDIM) return;
    int n = idx >> 8, k = idx & 255;
    float v = W[(size_t)k * Nn + n];
    __nv_bfloat16 h = __float2bfloat16(v);
    hi[idx] = h;
    lo[idx] = __float2bfloat16(v - __bfloat162float(h));
}

// ---------------- HMMA split-bf16 GEMM (unchanged from R6) ----------------
__global__ void __launch_bounds__(256, 2) gemm_mma(
    const __nv_bfloat16* __restrict__ Ahi, const __nv_bfloat16* __restrict__ Alo,
    const __nv_bfloat16* __restrict__ Bhi, const __nv_bfloat16* __restrict__ Blo,
    float* __restrict__ C, int M, int Nn)
{
    __shared__ __align__(16) char smem[43008];
    constexpr int A_HI = 0;
    constexpr int A_LO = 14336;
    constexpr int B_HI = 28672;
    constexpr int B_LO = 35840;

    const int tid  = threadIdx.x;
    const int lane = tid & 31;
    const int wid  = tid >> 5;
    const int warpRow = wid & 3;
    const int warpCol = wid >> 2;
    const int rowBase = blockIdx.x * 128;
    const int colBase = blockIdx.y * 64;

    float acc[2][4][4];
#pragma unroll
    for (int i = 0; i < 2; i++)
#pragma unroll
        for (int j = 0; j < 4; j++)
#pragma unroll
            for (int q = 0; q < 4; q++) acc[i][j][q] = 0.f;

    const uint32_t sb = s2u(smem);
    uint32_t aAdrH[2], aAdrL[2];
#pragma unroll
    for (int m16 = 0; m16 < 2; m16++) {
        uint32_t r = warpRow * 32 + m16 * 16 + (lane & 15);
        uint32_t cb = ((lane >> 4) * 8) * 2;
        aAdrH[m16] = sb + A_HI + r * 112 + cb;
        aAdrL[m16] = sb + A_LO + r * 112 + cb;
    }
    uint32_t bAdrH[2], bAdrL[2];
#pragma unroll
    for (int nbp = 0; nbp < 2; nbp++) {
        uint32_t r = warpCol * 32 + nbp * 16 + ((lane >> 4) << 3) + (lane & 7);
        uint32_t cb = (((lane >> 3) & 1) * 8) * 2;
        bAdrH[nbp] = sb + B_HI + r * 112 + cb;
        bAdrL[nbp] = sb + B_LO + r * 112 + cb;
    }

    for (int k0 = 0; k0 < KDIM; k0 += 32) {
#pragma unroll
        for (int it = 0; it < 2; it++) {
            int i = tid + it * 256;
            int r = i >> 2, c = (i & 3) * 8;
            uint4 vh = make_uint4(0, 0, 0, 0), vl = vh;
            int gr = rowBase + r;
            if (gr < M) {
                size_t g = (size_t)gr * KDIM + k0 + c;
                vh = *(const uint4*)(Ahi + g);
                vl = *(const uint4*)(Alo + g);
            }
            *(uint4*)(smem + A_HI + r * 112 + c * 2) = vh;
            *(uint4*)(smem + A_LO + r * 112 + c * 2) = vl;
        }
        {
            int r = tid >> 2, c = (tid & 3) * 8;
            size_t g = (size_t)(colBase + r) * KDIM + k0 + c;
            *(uint4*)(smem + B_HI + r * 112 + c * 2) = *(const uint4*)(Bhi + g);
            *(uint4*)(smem + B_LO + r * 112 + c * 2) = *(const uint4*)(Blo + g);
        }
        __syncthreads();

#pragma unroll
        for (int kk = 0; kk < 2; kk++) {
            const uint32_t kb = kk * 32;
            uint32_t ah[2][4], al[2][4], bh[2][4], bl[2][4];
            LDM4(ah[0], aAdrH[0] + kb);
            LDM4(ah[1], aAdrH[1] + kb);
            LDM4(al[0], aAdrL[0] + kb);
            LDM4(al[1], aAdrL[1] + kb);
            LDM4(bh[0], bAdrH[0] + kb);
            LDM4(bh[1], bAdrH[1] + kb);
            LDM4(bl[0], bAdrL[0] + kb);
            LDM4(bl[1], bAdrL[1] + kb);
#pragma unroll
            for (int m16 = 0; m16 < 2; m16++) {
#pragma unroll
                for (int nb = 0; nb < 4; nb++) {
                    const int p = nb >> 1, q = (nb & 1) * 2;
                    MMA_BF16(acc[m16][nb], ah[m16], bh[p][q], bh[p][q + 1]);
                    MMA_BF16(acc[m16][nb], ah[m16], bl[p][q], bl[p][q + 1]);
                    MMA_BF16(acc[m16][nb], al[m16], bh[p][q], bh[p][q + 1]);
                }
            }
        }
        __syncthreads();
    }

#pragma unroll
    for (int m16 = 0; m16 < 2; m16++) {
        int r0 = rowBase + warpRow * 32 + m16 * 16 + (lane >> 2);
#pragma unroll
        for (int nb = 0; nb < 4; nb++) {
            int col = colBase + warpCol * 32 + nb * 8 + (lane & 3) * 2;
            if (r0 < M)
                *(float2*)(C + (size_t)r0 * Nn + col) =
                    make_float2(acc[m16][nb][0], acc[m16][nb][1]);
            if (r0 + 8 < M)
                *(float2*)(C + (size_t)(r0 + 8) * Nn + col) =
                    make_float2(acc[m16][nb][2], acc[m16][nb][3]);
        }
    }
}

// ---------------- per-node attention logits (proj row stride = 256 always) --------
template <int H, int C>
__global__ void logits_kernel(const float* __restrict__ proj,
                              const float* __restrict__ a_s,
                              const float* __restrict__ a_d,
                              float* __restrict__ als, float* __restrict__ ald) {
    int w = (blockIdx.x * blockDim.x + threadIdx.x) >> 5;
    int lane = threadIdx.x & 31;
    if (w >= NN * H) return;
    int n = w / H, h = w % H;
    const float* p = proj + (size_t)n * 256 + h * C;
    float ss = 0.f, sd = 0.f;
#pragma unroll
    for (int c = lane; c < C; c += 32) {
        float v = p[c];
        ss = fmaf(v, a_s[h * C + c], ss);
        sd = fmaf(v, a_d[h * C + c], sd);
    }
#pragma unroll
    for (int o = 16; o > 0; o >>= 1) {
        ss += __shfl_xor_sync(0xffffffffu, ss, o);
        sd += __shfl_xor_sync(0xffffffffu, sd, o);
    }
    if (lane == 0) {
        als[n * H + h] = ss;
        ald[n * H + h] = sd;
    }
}

// ---------------- fused CSR aggregation, H=4, 256 ch: warp per dst ----------------
// self-loop init + gather-accumulate + softmax divide + bias (+res) + bf16 split, fused.
__global__ void gat_agg256(const float* __restrict__ proj,
                           const float* __restrict__ als, const float* __restrict__ ald,
                           const float* __restrict__ bias, const float* __restrict__ res,
                           float* __restrict__ outp,
                           __nv_bfloat16* __restrict__ hi, __nv_bfloat16* __restrict__ lo) {
    int w = (blockIdx.x * blockDim.x + threadIdx.x) >> 5;
    if (w >= NN) return;
    const int lane = threadIdx.x & 31;
    const int d = w;
    const float aldl = (lane < 4) ? ald[d * 4 + lane] : 0.f;

    float wt = 0.f, sden = 0.f;
    if (lane < 4) {
        wt = __expf(lrelu(als[d * 4 + lane] + aldl));
        sden = wt;
    }
    float wh = __shfl_sync(0xffffffffu, wt, lane >> 3);

    const float4* pr = (const float4*)proj;
    float4 a0, a1;
    {
        float4 p0 = pr[(size_t)d * 64 + lane * 2];
        float4 p1 = pr[(size_t)d * 64 + lane * 2 + 1];
        a0 = make_float4(wh * p0.x, wh * p0.y, wh * p0.z, wh * p0.w);
        a1 = make_float4(wh * p1.x, wh * p1.y, wh * p1.z, wh * p1.w);
    }
    const int jb = g_rowptr[d], je = g_rowptr[d + 1];
    int s = (jb < je) ? g_ssrc[jb] : 0;
    for (int j = jb; j < je; j++) {
        int sn = (j + 1 < je) ? g_ssrc[j + 1] : 0;
        float w2 = 0.f;
        if (lane < 4) {
            w2 = __expf(lrelu(als[s * 4 + lane] + aldl));
            sden += w2;
        }
        float wh2 = __shfl_sync(0xffffffffu, w2, lane >> 3);
        float4 p0 = pr[(size_t)s * 64 + lane * 2];
        float4 p1 = pr[(size_t)s * 64 + lane * 2 + 1];
        a0.x = fmaf(wh2, p0.x, a0.x); a0.y = fmaf(wh2, p0.y, a0.y);
        a0.z = fmaf(wh2, p0.z, a0.z); a0.w = fmaf(wh2, p0.w, a0.w);
        a1.x = fmaf(wh2, p1.x, a1.x); a1.y = fmaf(wh2, p1.y, a1.y);
        a1.z = fmaf(wh2, p1.z, a1.z); a1.w = fmaf(wh2, p1.w, a1.w);
        s = sn;
    }
    float inv = 1.0f / __shfl_sync(0xffffffffu, sden, lane >> 3);
    float4 b0 = ((const float4*)bias)[lane * 2];
    float4 b1 = ((const float4*)bias)[lane * 2 + 1];
    float o[8];
    o[0] = a0.x * inv + b0.x; o[1] = a0.y * inv + b0.y;
    o[2] = a0.z * inv + b0.z; o[3] = a0.w * inv + b0.w;
    o[4] = a1.x * inv + b1.x; o[5] = a1.y * inv + b1.y;
    o[6] = a1.z * inv + b1.z; o[7] = a1.w * inv + b1.w;
    if (res) {
        float4 r0 = ((const float4*)res)[(size_t)d * 64 + lane * 2];
        float4 r1 = ((const float4*)res)[(size_t)d * 64 + lane * 2 + 1];
        o[0] += r0.x; o[1] += r0.y; o[2] += r0.z; o[3] += r0.w;
        o[4] += r1.x; o[5] += r1.y; o[6] += r1.z; o[7] += r1.w;
    }
    if (outp) {
        ((float4*)outp)[(size_t)d * 64 + lane * 2] = make_float4(o[0], o[1], o[2], o[3]);
        ((float4*)outp)[(size_t)d * 64 + lane * 2 + 1] = make_float4(o[4], o[5], o[6], o[7]);
    }
    // fused bf16 hi/lo split for next layer's GEMM
    __nv_bfloat162 hv[4], lv[4];
#pragma unroll
    for (int q = 0; q < 4; q++) {
        __nv_bfloat16 h0b = __float2bfloat16(o[2 * q]);
        __nv_bfloat16 h1b = __float2bfloat16(o[2 * q + 1]);
        hv[q] = __nv_bfloat162(h0b, h1b);
        lv[q] = __nv_bfloat162(__float2bfloat16(o[2 * q] - __bfloat162float(h0b)),
                               __float2bfloat16(o[2 * q + 1] - __bfloat162float(h1b)));
    }
    *(uint4*)(hi + (size_t)d * 256 + lane * 8) = *(uint4*)hv;
    *(uint4*)(lo + (size_t)d * 256 + lane * 8) = *(uint4*)lv;
}

// ---------------- fused CSR aggregation, H=1, 128 ch (layer 2) ----------------
// proj row = [h (128) | lin (128)], stride 256. out = agg/sden + b2 + bl + lin.
__global__ void gat_agg128(const float* __restrict__ proj,
                           const float* __restrict__ als, const float* __restrict__ ald,
                           const float* __restrict__ bias, const float* __restrict__ bias2,
                           float* __restrict__ outp) {
    int w = (blockIdx.x * blockDim.x + threadIdx.x) >> 5;
    if (w >= NN) return;
    const int lane = threadIdx.x & 31;
    const int d = w;
    const float aldv = __shfl_sync(0xffffffffu, (lane == 0) ? ald[d] : 0.f, 0);

    float wt = 0.f, sden = 0.f;
    if (lane == 0) {
        wt = __expf(lrelu(als[d] + aldv));
        sden = wt;
    }
    float wh = __shfl_sync(0xffffffffu, wt, 0);
    const float4* pr = (const float4*)proj;
    float4 a0;
    {
        float4 p = pr[(size_t)d * 64 + lane];
        a0 = make_float4(wh * p.x, wh * p.y, wh * p.z, wh * p.w);
    }
    const int jb = g_rowptr[d], je = g_rowptr[d + 1];
    int s = (jb < je) ? g_ssrc[jb] : 0;
    for (int j = jb; j < je; j++) {
        int sn = (j + 1 < je) ? g_ssrc[j + 1] : 0;
        float w2 = 0.f;
        if (lane == 0) {
            w2 = __expf(lrelu(als[s] + aldv));
            sden += w2;
        }
        float wh2 = __shfl_sync(0xffffffffu, w2, 0);
        float4 p = pr[(size_t)s * 64 + lane];
        a0.x = fmaf(wh2, p.x, a0.x); a0.y = fmaf(wh2, p.y, a0.y);
        a0.z = fmaf(wh2, p.z, a0.z); a0.w = fmaf(wh2, p.w, a0.w);
        s = sn;
    }
    float inv = 1.0f / __shfl_sync(0xffffffffu, sden, 0);
    float4 b0 = ((const float4*)bias)[lane];
    float4 b2 = ((const float4*)bias2)[lane];
    float4 l0 = pr[(size_t)d * 64 + 32 + lane];   // lin = cols 128..255
    float4 o = make_float4(a0.x * inv + b0.x + b2.x + l0.x,
                           a0.y * inv + b0.y + b2.y + l0.y,
                           a0.z * inv + b0.z + b2.z + l0.z,
                           a0.w * inv + b0.w + b2.w + l0.w);
    ((float4*)outp)[(size_t)d * 32 + lane] = o;
}

// ---------------- host orchestration ----------------
extern "C" void kernel_launch(void* const* d_in, const int* in_sizes, int n_in,
                              void* d_out, int out_size) {
    const float* x   = (const float*)d_in[0];
    const void*  ei  = d_in[1];
    const float* W0  = (const float*)d_in[2];
    const float* as0 = (const float*)d_in[3];
    const float* ad0 = (const float*)d_in[4];
    const float* b0  = (const float*)d_in[5];
    const float* W1  = (const float*)d_in[6];
    const float* as1 = (const float*)d_in[7];
    const float* ad1 = (const float*)d_in[8];
    const float* b1  = (const float*)d_in[9];
    const float* W2  = (const float*)d_in[10];
    const float* as2 = (const float*)d_in[11];
    const float* ad2 = (const float*)d_in[12];
    const float* b2  = (const float*)d_in[13];
    const float* Wl  = (const float*)d_in[14];
    const float* bl  = (const float*)d_in[15];
    float* out = (float*)d_out;
    const int E = in_sizes[1] / 2;

    float *p_proj, *p_h0, *p_als, *p_ald;
    __nv_bfloat16 *p_ahi, *p_alo, *p_w0hi, *p_w0lo, *p_w1hi, *p_w1lo, *p_wchi, *p_wclo;
    cudaGetSymbolAddress((void**)&p_proj, g_proj);
    cudaGetSymbolAddress((void**)&p_h0,   g_h0);
    cudaGetSymbolAddress((void**)&p_als,  g_als);
    cudaGetSymbolAddress((void**)&p_ald,  g_ald);
    cudaGetSymbolAddress((void**)&p_ahi,  g_ahi);
    cudaGetSymbolAddress((void**)&p_alo,  g_alo);
    cudaGetSymbolAddress((void**)&p_w0hi, g_w0hi);
    cudaGetSymbolAddress((void**)&p_w0lo, g_w0lo);
    cudaGetSymbolAddress((void**)&p_w1hi, g_w1hi);
    cudaGetSymbolAddress((void**)&p_w1lo, g_w1lo);
    cudaGetSymbolAddress((void**)&p_wchi, g_wchi);
    cudaGetSymbolAddress((void**)&p_wclo, g_wclo);

    // ---- CSR build (every call; deterministic work) ----
    probe_kernel<<<1, 32>>>((const int*)ei, E > 1024 ? 1024 : E);
    zero_cnt<<<(NN + 255) / 256, 256>>>();
    convert_hist<<<(E + 255) / 256, 256>>>(ei, E);
    scan_kernel<<<1, 1024>>>();
    scatter_kernel<<<(E + 255) / 256, 256>>>(E);

    // ---- weight prep: transpose + bf16 split ----
    wsplit<<<(HC * KDIM + 255) / 256, 256>>>(W0, HC, p_w0hi, p_w0lo);
    wsplit<<<(HC * KDIM + 255) / 256, 256>>>(W1, HC, p_w1hi, p_w1lo);
    wsplit<<<(OUTC * KDIM + 255) / 256, 256>>>(W2, OUTC, p_wchi, p_wclo);
    wsplit<<<(OUTC * KDIM + 255) / 256, 256>>>(Wl, OUTC, p_wchi + (size_t)OUTC * KDIM,
                                               p_wclo + (size_t)OUTC * KDIM);

    const int GEMM_BX = (NN + 127) / 128;
    const int total4 = NN * KDIM / 4;
    const int AGG_BLKS = (NN * 32 + 255) / 256;

    // ---- layer 0: x -> h0 (float + bf16 split) ----
    split_act<<<(total4 + 255) / 256, 256>>>(x, p_ahi, p_alo, total4);
    gemm_mma<<<dim3(GEMM_BX, 4), 256>>>(p_ahi, p_alo, p_w0hi, p_w0lo, p_proj, NN, HC);
    logits_kernel<4, 64><<<(NN * 4 * 32 + 255) / 256, 256>>>(p_proj, as0, ad0, p_als, p_ald);
    gat_agg256<<<AGG_BLKS, 256>>>(p_proj, p_als, p_ald, b0, nullptr, p_h0, p_ahi, p_alo);

    // ---- layer 1: h0 -> h1 (residual h0; h1 only needed as bf16 split) ----
    gemm_mma<<<dim3(GEMM_BX, 4), 256>>>(p_ahi, p_alo, p_w1hi, p_w1lo, p_proj, NN, HC);
    logits_kernel<4, 64><<<(NN * 4 * 32 + 255) / 256, 256>>>(p_proj, as1, ad1, p_als, p_ald);
    gat_agg256<<<AGG_BLKS, 256>>>(p_proj, p_als, p_ald, b1, p_h0, nullptr, p_ahi, p_alo);

    // ---- layer 2: combined [W2 | Wl] GEMM, then fused agg + lin + biases ----
    gemm_mma<<<dim3(GEMM_BX, 4), 256>>>(p_ahi, p_alo, p_wchi, p_wclo, p_proj, NN, 256);
    logits_kernel<1, 128><<<(NN * 32 + 255) / 256, 256>>>(p_proj, as2, ad2, p_als, p_ald);
    gat_agg128<<<AGG_BLKS, 256>>>(p_proj, p_als, p_ald, b2, bl, out);
}

// round 8
// speedup vs baseline: 2.6635x; 1.1274x over previous
#include <cuda_runtime.h>
#include <cuda_bf16.h>
#include <cstdint>

// ---------------- constants ----------------
#define NN      50000
#define MAXE    2000000
#define HEADS   4
#define HC      256          // HEADS*HID
#define OUTC    128
#define KDIM    256          // all GEMMs have K=256
#define NB_SCAN ((NN + 255) / 256)

// ---------------- device scratch ----------------
__device__ float    g_proj[(size_t)NN * HC];
__device__ float    g_h0  [(size_t)NN * HC];
__device__ float    g_als [NN * HEADS];
__device__ float    g_ald [NN * HEADS];
__device__ int      g_src [MAXE];
__device__ int      g_dst [MAXE];
__device__ int      g_ssrc[MAXE];
__device__ int      g_cnt [NN];
__device__ int      g_tmp [NN];
__device__ int      g_bsum[256];
__device__ int      g_boff[256];
__device__ int      g_cursor[NN];
__device__ int      g_rowptr[NN + 1];
__device__ int      g_is64;
// bf16 split activations (reused across layers) and transposed split weights [N,K]
__device__ __nv_bfloat16 g_ahi[(size_t)NN * KDIM];
__device__ __nv_bfloat16 g_alo[(size_t)NN * KDIM];
__device__ __nv_bfloat16 g_w0hi[KDIM * HC],  g_w0lo[KDIM * HC];
__device__ __nv_bfloat16 g_w1hi[KDIM * HC],  g_w1lo[KDIM * HC];
__device__ __nv_bfloat16 g_wchi[KDIM * 256], g_wclo[KDIM * 256];  // [W2 | Wl] combined

// ---------------- helpers ----------------
__device__ __forceinline__ float lrelu(float v) { return v > 0.f ? v : 0.2f * v; }

__device__ __forceinline__ uint32_t s2u(const void* p) {
    uint32_t a;
    asm("{ .reg .u64 t; cvta.to.shared.u64 t, %1; cvt.u32.u64 %0, t; }" : "=r"(a) : "l"(p));
    return a;
}

#define LDM4(d, addr) \
    asm volatile("ldmatrix.sync.aligned.m8n8.x4.shared.b16 {%0,%1,%2,%3}, [%4];" \
        : "=r"((d)[0]), "=r"((d)[1]), "=r"((d)[2]), "=r"((d)[3]) : "r"(addr))

#define MMA_BF16(c, a, b0, b1) \
    asm volatile("mma.sync.aligned.m16n8k16.row.col.f32.bf16.bf16.f32 " \
        "{%0,%1,%2,%3}, {%4,%5,%6,%7}, {%8,%9}, {%0,%1,%2,%3};" \
        : "+f"((c)[0]), "+f"((c)[1]), "+f"((c)[2]), "+f"((c)[3]) \
        : "r"((a)[0]), "r"((a)[1]), "r"((a)[2]), "r"((a)[3]), "r"(b0), "r"(b1))

// ---------------- edge index prep: dtype normalize + dst histogram ----------------
__global__ void probe_kernel(const int* p32, int nchk) {
    if (blockIdx.x == 0 && threadIdx.x == 0) {
        int z = 0;
        for (int k = 0; k < nchk; k++)
            if (p32[2 * k + 1] == 0) z++;
        g_is64 = (z * 2 > nchk) ? 1 : 0;
    }
}

__global__ void zero_cnt() {
    int i = blockIdx.x * blockDim.x + threadIdx.x;
    if (i < NN) g_cnt[i] = 0;
}

__global__ void convert_hist(const void* ei, int E) {
    int e = blockIdx.x * blockDim.x + threadIdx.x;
    if (e >= E || e >= MAXE) return;
    int s, d;
    if (g_is64) {
        const long long* p = (const long long*)ei;
        s = (int)p[e];
        d = (int)p[(size_t)E + e];
    } else {
        const int* p = (const int*)ei;
        s = p[e];
        d = p[E + e];
    }
    g_src[e] = s;
    g_dst[e] = d;
    atomicAdd(&g_cnt[d], 1);
}

// ---------------- 3-phase exclusive scan: g_cnt -> g_rowptr / g_cursor ----------------
__global__ void scanA() {
    int i = blockIdx.x * 256 + threadIdx.x;
    int lane = threadIdx.x & 31, warp = threadIdx.x >> 5;
    int v = (i < NN) ? g_cnt[i] : 0;
    int x = v;
#pragma unroll
    for (int off = 1; off < 32; off <<= 1) {
        int t = __shfl_up_sync(0xffffffffu, x, off);
        if (lane >= off) x += t;
    }
    __shared__ int ws[8];
    if (lane == 31) ws[warp] = x;
    __syncthreads();
    if (threadIdx.x == 0) {
        int run = 0;
#pragma unroll
        for (int j = 0; j < 8; j++) { int t = ws[j]; ws[j] = run; run += t; }
        g_bsum[blockIdx.x] = run;
    }
    __syncthreads();
    if (i < NN) g_tmp[i] = x - v + ws[warp];
}

__global__ void scanB(int nb) {
    int tid = threadIdx.x, lane = tid & 31, warp = tid >> 5;
    int v = (tid < nb) ? g_bsum[tid] : 0;
    int x = v;
#pragma unroll
    for (int off = 1; off < 32; off <<= 1) {
        int t = __shfl_up_sync(0xffffffffu, x, off);
        if (lane >= off) x += t;
    }
    __shared__ int ws[8];
    if (lane == 31) ws[warp] = x;
    __syncthreads();
    if (tid == 0) {
        int run = 0;
#pragma unroll
        for (int j = 0; j < 8; j++) { int t = ws[j]; ws[j] = run; run += t; }
        g_rowptr[NN] = run;
    }
    __syncthreads();
    g_boff[tid] = x - v + ws[warp];
}

__global__ void scanC() {
    int i = blockIdx.x * 256 + threadIdx.x;
    if (i < NN) {
        int r = g_tmp[i] + g_boff[blockIdx.x];
        g_rowptr[i] = r;
        g_cursor[i] = r;
    }
}

__global__ void scatter_kernel(int E) {
    int e = blockIdx.x * blockDim.x + threadIdx.x;
    if (e >= E || e >= MAXE) return;
    int pos = atomicAdd(&g_cursor[g_dst[e]], 1);
    g_ssrc[pos] = g_src[e];
}

__global__ void zero_als(float* als, float* ald) {
    int i = blockIdx.x * blockDim.x + threadIdx.x;
    if (i < NN) { als[i] = 0.f; ald[i] = 0.f; }
}

// ---------------- bf16 hi/lo split (layer-0 input only) ----------------
__global__ void split_act(const float* __restrict__ in, __nv_bfloat16* __restrict__ hi,
                          __nv_bfloat16* __restrict__ lo, int total4) {
    int i = blockIdx.x * blockDim.x + threadIdx.x;
    if (i >= total4) return;
    float4 v = ((const float4*)in)[i];
    float vv[4] = {v.x, v.y, v.z, v.w};
    __nv_bfloat16 h[4], l[4];
#pragma unroll
    for (int j = 0; j < 4; j++) {
        h[j] = __float2bfloat16(vv[j]);
        l[j] = __float2bfloat16(vv[j] - __bfloat162float(h[j]));
    }
    ((__nv_bfloat162*)hi)[2 * i]     = __nv_bfloat162(h[0], h[1]);
    ((__nv_bfloat162*)hi)[2 * i + 1] = __nv_bfloat162(h[2], h[3]);
    ((__nv_bfloat162*)lo)[2 * i]     = __nv_bfloat162(l[0], l[1]);
    ((__nv_bfloat162*)lo)[2 * i + 1] = __nv_bfloat162(l[2], l[3]);
}

// ---------------- weight transpose + split: W[K,N] -> Wt[N,K] hi/lo ----------------
__global__ void wsplit(const float* __restrict__ W, int Nn,
                       __nv_bfloat16* __restrict__ hi, __nv_bfloat16* __restrict__ lo) {
    int idx = blockIdx.x * blockDim.x + threadIdx.x;   // n*256 + k
    if (idx >= Nn * KDIM) return;
    int n = idx >> 8, k = idx & 255;
    float v = W[(size_t)k * Nn + n];
    __nv_bfloat16 h = __float2bfloat16(v);
    hi[idx] = h;
    lo[idx] = __float2bfloat16(v - __bfloat162float(h));
}

// ---------------- HMMA split-bf16 GEMM with fused attention logits ----------------
// lmode: 0 = plain GEMM; 1 = y-block == head, store als[row*4+y]/ald;
//        2 = y<2 are halves of a single 128-ch head -> atomicAdd into als[row]/ald[row]
__global__ void __launch_bounds__(256, 2) gemm_mma(
    const __nv_bfloat16* __restrict__ Ahi, const __nv_bfloat16* __restrict__ Alo,
    const __nv_bfloat16* __restrict__ Bhi, const __nv_bfloat16* __restrict__ Blo,
    float* __restrict__ C, int M, int Nn,
    int lmode, const float* __restrict__ a_s, const float* __restrict__ a_d,
    float* __restrict__ als, float* __restrict__ ald)
{
    __shared__ __align__(16) char smem[43008];
    __shared__ float red_ss[128], red_sd[128];
    constexpr int A_HI = 0;
    constexpr int A_LO = 14336;
    constexpr int B_HI = 28672;
    constexpr int B_LO = 35840;

    const int tid  = threadIdx.x;
    const int lane = tid & 31;
    const int wid  = tid >> 5;
    const int warpRow = wid & 3;
    const int warpCol = wid >> 2;
    const int rowBase = blockIdx.x * 128;
    const int colBase = blockIdx.y * 64;

    float acc[2][4][4];
#pragma unroll
    for (int i = 0; i < 2; i++)
#pragma unroll
        for (int j = 0; j < 4; j++)
#pragma unroll
            for (int q = 0; q < 4; q++) acc[i][j][q] = 0.f;

    const uint32_t sb = s2u(smem);
    uint32_t aAdrH[2], aAdrL[2];
#pragma unroll
    for (int m16 = 0; m16 < 2; m16++) {
        uint32_t r = warpRow * 32 + m16 * 16 + (lane & 15);
        uint32_t cb = ((lane >> 4) * 8) * 2;
        aAdrH[m16] = sb + A_HI + r * 112 + cb;
        aAdrL[m16] = sb + A_LO + r * 112 + cb;
    }
    uint32_t bAdrH[2], bAdrL[2];
#pragma unroll
    for (int nbp = 0; nbp < 2; nbp++) {
        uint32_t r = warpCol * 32 + nbp * 16 + ((lane >> 4) << 3) + (lane & 7);
        uint32_t cb = (((lane >> 3) & 1) * 8) * 2;
        bAdrH[nbp] = sb + B_HI + r * 112 + cb;
        bAdrL[nbp] = sb + B_LO + r * 112 + cb;
    }

    for (int k0 = 0; k0 < KDIM; k0 += 32) {
#pragma unroll
        for (int it = 0; it < 2; it++) {
            int i = tid + it * 256;
            int r = i >> 2, c = (i & 3) * 8;
            uint4 vh = make_uint4(0, 0, 0, 0), vl = vh;
            int gr = rowBase + r;
            if (gr < M) {
                size_t g = (size_t)gr * KDIM + k0 + c;
                vh = *(const uint4*)(Ahi + g);
                vl = *(const uint4*)(Alo + g);
            }
            *(uint4*)(smem + A_HI + r * 112 + c * 2) = vh;
            *(uint4*)(smem + A_LO + r * 112 + c * 2) = vl;
        }
        {
            int r = tid >> 2, c = (tid & 3) * 8;
            size_t g = (size_t)(colBase + r) * KDIM + k0 + c;
            *(uint4*)(smem + B_HI + r * 112 + c * 2) = *(const uint4*)(Bhi + g);
            *(uint4*)(smem + B_LO + r * 112 + c * 2) = *(const uint4*)(Blo + g);
        }
        __syncthreads();

#pragma unroll
        for (int kk = 0; kk < 2; kk++) {
            const uint32_t kb = kk * 32;
            uint32_t ah[2][4], al[2][4], bh[2][4], bl[2][4];
            LDM4(ah[0], aAdrH[0] + kb);
            LDM4(ah[1], aAdrH[1] + kb);
            LDM4(al[0], aAdrL[0] + kb);
            LDM4(al[1], aAdrL[1] + kb);
            LDM4(bh[0], bAdrH[0] + kb);
            LDM4(bh[1], bAdrH[1] + kb);
            LDM4(bl[0], bAdrL[0] + kb);
            LDM4(bl[1], bAdrL[1] + kb);
#pragma unroll
            for (int m16 = 0; m16 < 2; m16++) {
#pragma unroll
                for (int nb = 0; nb < 4; nb++) {
                    const int p = nb >> 1, q = (nb & 1) * 2;
                    MMA_BF16(acc[m16][nb], ah[m16], bh[p][q], bh[p][q + 1]);
                    MMA_BF16(acc[m16][nb], ah[m16], bl[p][q], bl[p][q + 1]);
                    MMA_BF16(acc[m16][nb], al[m16], bh[p][q], bh[p][q + 1]);
                }
            }
        }
        __syncthreads();
    }

    // ---- store C ----
#pragma unroll
    for (int m16 = 0; m16 < 2; m16++) {
        int r0 = rowBase + warpRow * 32 + m16 * 16 + (lane >> 2);
#pragma unroll
        for (int nb = 0; nb < 4; nb++) {
            int col = colBase + warpCol * 32 + nb * 8 + (lane & 3) * 2;
            if (r0 < M)
                *(float2*)(C + (size_t)r0 * Nn + col) =
                    make_float2(acc[m16][nb][0], acc[m16][nb][1]);
            if (r0 + 8 < M)
                *(float2*)(C + (size_t)(r0 + 8) * Nn + col) =
                    make_float2(acc[m16][nb][2], acc[m16][nb][3]);
        }
    }

    // ---- fused attention logits ----
    if (lmode == 1 || (lmode == 2 && blockIdx.y < 2)) {
        const int y = blockIdx.y;
        float pss[2][2] = {{0.f, 0.f}, {0.f, 0.f}};
        float psd[2][2] = {{0.f, 0.f}, {0.f, 0.f}};
#pragma unroll
        for (int m16 = 0; m16 < 2; m16++) {
#pragma unroll
            for (int nb = 0; nb < 4; nb++) {
                int cl = warpCol * 32 + nb * 8 + (lane & 3) * 2;
                float s0 = __ldg(a_s + y * 64 + cl), s1 = __ldg(a_s + y * 64 + cl + 1);
                float d0 = __ldg(a_d + y * 64 + cl), d1 = __ldg(a_d + y * 64 + cl + 1);
                pss[m16][0] += acc[m16][nb][0] * s0 + acc[m16][nb][1] * s1;
                psd[m16][0] += acc[m16][nb][0] * d0 + acc[m16][nb][1] * d1;
                pss[m16][1] += acc[m16][nb][2] * s0 + acc[m16][nb][3] * s1;
                psd[m16][1] += acc[m16][nb][2] * d0 + acc[m16][nb][3] * d1;
            }
        }
#pragma unroll
        for (int m16 = 0; m16 < 2; m16++)
#pragma unroll
            for (int hh = 0; hh < 2; hh++) {
                pss[m16][hh] += __shfl_xor_sync(0xffffffffu, pss[m16][hh], 1);
                pss[m16][hh] += __shfl_xor_sync(0xffffffffu, pss[m16][hh], 2);
                psd[m16][hh] += __shfl_xor_sync(0xffffffffu, psd[m16][hh], 1);
                psd[m16][hh] += __shfl_xor_sync(0xffffffffu, psd[m16][hh], 2);
            }
        if (warpCol == 0 && (lane & 3) == 0) {
#pragma unroll
            for (int m16 = 0; m16 < 2; m16++)
#pragma unroll
                for (int hh = 0; hh < 2; hh++) {
                    int rb = warpRow * 32 + m16 * 16 + hh * 8 + (lane >> 2);
                    red_ss[rb] = pss[m16][hh];
                    red_sd[rb] = psd[m16][hh];
                }
        }
        __syncthreads();
        if (warpCol == 1 && (lane & 3) == 0) {
#pragma unroll
            for (int m16 = 0; m16 < 2; m16++)
#pragma unroll
                for (int hh = 0; hh < 2; hh++) {
                    int rb = warpRow * 32 + m16 * 16 + hh * 8 + (lane >> 2);
                    int row = rowBase + rb;
                    if (row < M) {
                        float S = red_ss[rb] + pss[m16][hh];
                        float D = red_sd[rb] + psd[m16][hh];
                        if (lmode == 1) {
                            als[row * 4 + y] = S;
                            ald[row * 4 + y] = D;
                        } else {
                            atomicAdd(&als[row], S);
                            atomicAdd(&ald[row], D);
                        }
                    }
                }
        }
    }
}

// ---------------- fused CSR aggregation, H=4, 256 ch: warp per dst ----------------
__global__ void gat_agg256(const float* __restrict__ proj,
                           const float* __restrict__ als, const float* __restrict__ ald,
                           const float* __restrict__ bias, const float* __restrict__ res,
                           float* __restrict__ outp,
                           __nv_bfloat16* __restrict__ hi, __nv_bfloat16* __restrict__ lo) {
    int w = (blockIdx.x * blockDim.x + threadIdx.x) >> 5;
    if (w >= NN) return;
    const int lane = threadIdx.x & 31;
    const int d = w;
    const float aldl = (lane < 4) ? ald[d * 4 + lane] : 0.f;

    float wt = 0.f, sden = 0.f;
    if (lane < 4) {
        wt = __expf(lrelu(als[d * 4 + lane] + aldl));
        sden = wt;
    }
    float wh = __shfl_sync(0xffffffffu, wt, lane >> 3);

    const float4* pr = (const float4*)proj;
    float4 a0, a1;
    {
        float4 p0 = pr[(size_t)d * 64 + lane * 2];
        float4 p1 = pr[(size_t)d * 64 + lane * 2 + 1];
        a0 = make_float4(wh * p0.x, wh * p0.y, wh * p0.z, wh * p0.w);
        a1 = make_float4(wh * p1.x, wh * p1.y, wh * p1.z, wh * p1.w);
    }
    const int jb = g_rowptr[d], je = g_rowptr[d + 1];
    int s = (jb < je) ? g_ssrc[jb] : 0;
    for (int j = jb; j < je; j++) {
        int sn = (j + 1 < je) ? g_ssrc[j + 1] : 0;
        float w2 = 0.f;
        if (lane < 4) {
            w2 = __expf(lrelu(als[s * 4 + lane] + aldl));
            sden += w2;
        }
        float wh2 = __shfl_sync(0xffffffffu, w2, lane >> 3);
        float4 p0 = pr[(size_t)s * 64 + lane * 2];
        float4 p1 = pr[(size_t)s * 64 + lane * 2 + 1];
        a0.x = fmaf(wh2, p0.x, a0.x); a0.y = fmaf(wh2, p0.y, a0.y);
        a0.z = fmaf(wh2, p0.z, a0.z); a0.w = fmaf(wh2, p0.w, a0.w);
        a1.x = fmaf(wh2, p1.x, a1.x); a1.y = fmaf(wh2, p1.y, a1.y);
        a1.z = fmaf(wh2, p1.z, a1.z); a1.w = fmaf(wh2, p1.w, a1.w);
        s = sn;
    }
    float inv = 1.0f / __shfl_sync(0xffffffffu, sden, lane >> 3);
    float4 b0 = ((const float4*)bias)[lane * 2];
    float4 b1 = ((const float4*)bias)[lane * 2 + 1];
    float o[8];
    o[0] = a0.x * inv + b0.x; o[1] = a0.y * inv + b0.y;
    o[2] = a0.z * inv + b0.z; o[3] = a0.w * inv + b0.w;
    o[4] = a1.x * inv + b1.x; o[5] = a1.y * inv + b1.y;
    o[6] = a1.z * inv + b1.z; o[7] = a1.w * inv + b1.w;
    if (res) {
        float4 r0 = ((const float4*)res)[(size_t)d * 64 + lane * 2];
        float4 r1 = ((const float4*)res)[(size_t)d * 64 + lane * 2 + 1];
        o[0] += r0.x; o[1] += r0.y; o[2] += r0.z; o[3] += r0.w;
        o[4] += r1.x; o[5] += r1.y; o[6] += r1.z; o[7] += r1.w;
    }
    if (outp) {
        ((float4*)outp)[(size_t)d * 64 + lane * 2] = make_float4(o[0], o[1], o[2], o[3]);
        ((float4*)outp)[(size_t)d * 64 + lane * 2 + 1] = make_float4(o[4], o[5], o[6], o[7]);
    }
    __nv_bfloat162 hv[4], lv[4];
#pragma unroll
    for (int q = 0; q < 4; q++) {
        __nv_bfloat16 h0b = __float2bfloat16(o[2 * q]);
        __nv_bfloat16 h1b = __float2bfloat16(o[2 * q + 1]);
        hv[q] = __nv_bfloat162(h0b, h1b);
        lv[q] = __nv_bfloat162(__float2bfloat16(o[2 * q] - __bfloat162float(h0b)),
                               __float2bfloat16(o[2 * q + 1] - __bfloat162float(h1b)));
    }
    *(uint4*)(hi + (size_t)d * 256 + lane * 8) = *(uint4*)hv;
    *(uint4*)(lo + (size_t)d * 256 + lane * 8) = *(uint4*)lv;
}

// ---------------- fused CSR aggregation, H=1, 128 ch (layer 2) ----------------
__global__ void gat_agg128(const float* __restrict__ proj,
                           const float* __restrict__ als, const float* __restrict__ ald,
                           const float* __restrict__ bias, const float* __restrict__ bias2,
                           float* __restrict__ outp) {
    int w = (blockIdx.x * blockDim.x + threadIdx.x) >> 5;
    if (w >= NN) return;
    const int lane = threadIdx.x & 31;
    const int d = w;
    const float aldv = __shfl_sync(0xffffffffu, (lane == 0) ? ald[d] : 0.f, 0);

    float wt = 0.f, sden = 0.f;
    if (lane == 0) {
        wt = __expf(lrelu(als[d] + aldv));
        sden = wt;
    }
    float wh = __shfl_sync(0xffffffffu, wt, 0);
    const float4* pr = (const float4*)proj;
    float4 a0;
    {
        float4 p = pr[(size_t)d * 64 + lane];
        a0 = make_float4(wh * p.x, wh * p.y, wh * p.z, wh * p.w);
    }
    const int jb = g_rowptr[d], je = g_rowptr[d + 1];
    int s = (jb < je) ? g_ssrc[jb] : 0;
    for (int j = jb; j < je; j++) {
        int sn = (j + 1 < je) ? g_ssrc[j + 1] : 0;
        float w2 = 0.f;
        if (lane == 0) {
            w2 = __expf(lrelu(als[s] + aldv));
            sden += w2;
        }
        float wh2 = __shfl_sync(0xffffffffu, w2, 0);
        float4 p = pr[(size_t)s * 64 + lane];
        a0.x = fmaf(wh2, p.x, a0.x); a0.y = fmaf(wh2, p.y, a0.y);
        a0.z = fmaf(wh2, p.z, a0.z); a0.w = fmaf(wh2, p.w, a0.w);
        s = sn;
    }
    float inv = 1.0f / __shfl_sync(0xffffffffu, sden, 0);
    float4 b0 = ((const float4*)bias)[lane];
    float4 b2 = ((const float4*)bias2)[lane];
    float4 l0 = pr[(size_t)d * 64 + 32 + lane];
    float4 o = make_float4(a0.x * inv + b0.x + b2.x + l0.x,
                           a0.y * inv + b0.y + b2.y + l0.y,
                           a0.z * inv + b0.z + b2.z + l0.z,
                           a0.w * inv + b0.w + b2.w + l0.w);
    ((float4*)outp)[(size_t)d * 32 + lane] = o;
}

// ---------------- host orchestration ----------------
extern "C" void kernel_launch(void* const* d_in, const int* in_sizes, int n_in,
                              void* d_out, int out_size) {
    const float* x   = (const float*)d_in[0];
    const void*  ei  = d_in[1];
    const float* W0  = (const float*)d_in[2];
    const float* as0 = (const float*)d_in[3];
    const float* ad0 = (const float*)d_in[4];
    const float* b0  = (const float*)d_in[5];
    const float* W1  = (const float*)d_in[6];
    const float* as1 = (const float*)d_in[7];
    const float* ad1 = (const float*)d_in[8];
    const float* b1  = (const float*)d_in[9];
    const float* W2  = (const float*)d_in[10];
    const float* as2 = (const float*)d_in[11];
    const float* ad2 = (const float*)d_in[12];
    const float* b2  = (const float*)d_in[13];
    const float* Wl  = (const float*)d_in[14];
    const float* bl  = (const float*)d_in[15];
    float* out = (float*)d_out;
    const int E = in_sizes[1] / 2;

    float *p_proj, *p_h0, *p_als, *p_ald;
    __nv_bfloat16 *p_ahi, *p_alo, *p_w0hi, *p_w0lo, *p_w1hi, *p_w1lo, *p_wchi, *p_wclo;
    cudaGetSymbolAddress((void**)&p_proj, g_proj);
    cudaGetSymbolAddress((void**)&p_h0,   g_h0);
    cudaGetSymbolAddress((void**)&p_als,  g_als);
    cudaGetSymbolAddress((void**)&p_ald,  g_ald);
    cudaGetSymbolAddress((void**)&p_ahi,  g_ahi);
    cudaGetSymbolAddress((void**)&p_alo,  g_alo);
    cudaGetSymbolAddress((void**)&p_w0hi, g_w0hi);
    cudaGetSymbolAddress((void**)&p_w0lo, g_w0lo);
    cudaGetSymbolAddress((void**)&p_w1hi, g_w1hi);
    cudaGetSymbolAddress((void**)&p_w1lo, g_w1lo);
    cudaGetSymbolAddress((void**)&p_wchi, g_wchi);
    cudaGetSymbolAddress((void**)&p_wclo, g_wclo);

    // ---- CSR build (every call; deterministic work) ----
    probe_kernel<<<1, 32>>>((const int*)ei, E > 1024 ? 1024 : E);
    zero_cnt<<<NB_SCAN, 256>>>();
    convert_hist<<<(E + 255) / 256, 256>>>(ei, E);
    scanA<<<NB_SCAN, 256>>>();
    scanB<<<1, 256>>>(NB_SCAN);
    scanC<<<NB_SCAN, 256>>>();
    scatter_kernel<<<(E + 255) / 256, 256>>>(E);

    // ---- weight prep: transpose + bf16 split ----
    wsplit<<<(HC * KDIM + 255) / 256, 256>>>(W0, HC, p_w0hi, p_w0lo);
    wsplit<<<(HC * KDIM + 255) / 256, 256>>>(W1, HC, p_w1hi, p_w1lo);
    wsplit<<<(OUTC * KDIM + 255) / 256, 256>>>(W2, OUTC, p_wchi, p_wclo);
    wsplit<<<(OUTC * KDIM + 255) / 256, 256>>>(Wl, OUTC, p_wchi + (size_t)OUTC * KDIM,
                                               p_wclo + (size_t)OUTC * KDIM);

    const int GEMM_BX = (NN + 127) / 128;
    const int total4 = NN * KDIM / 4;
    const int AGG_BLKS = (NN * 32 + 255) / 256;

    // ---- layer 0: x -> h0 (float + bf16 split), logits fused in GEMM ----
    split_act<<<(total4 + 255) / 256, 256>>>(x, p_ahi, p_alo, total4);
    gemm_mma<<<dim3(GEMM_BX, 4), 256>>>(p_ahi, p_alo, p_w0hi, p_w0lo, p_proj, NN, HC,
                                        1, as0, ad0, p_als, p_ald);
    gat_agg256<<<AGG_BLKS, 256>>>(p_proj, p_als, p_ald, b0, nullptr, p_h0, p_ahi, p_alo);

    // ---- layer 1: h0 -> h1 (residual h0; h1 only needed as bf16 split) ----
    gemm_mma<<<dim3(GEMM_BX, 4), 256>>>(p_ahi, p_alo, p_w1hi, p_w1lo, p_proj, NN, HC,
                                        1, as1, ad1, p_als, p_ald);
    gat_agg256<<<AGG_BLKS, 256>>>(p_proj, p_als, p_ald, b1, p_h0, nullptr, p_ahi, p_alo);

    // ---- layer 2: combined [W2 | Wl] GEMM (logits via atomic halves), fused agg ----
    zero_als<<<NB_SCAN, 256>>>(p_als, p_ald);
    gemm_mma<<<dim3(GEMM_BX, 4), 256>>>(p_ahi, p_alo, p_wchi, p_wclo, p_proj, NN, 256,
                                        2, as2, ad2, p_als, p_ald);
    gat_agg128<<<AGG_BLKS, 256>>>(p_proj, p_als, p_ald, b2, bl, out);
}

// round 9
// speedup vs baseline: 2.9694x; 1.1148x over previous
#include <cuda_runtime.h>
#include <cuda_bf16.h>
#include <cstdint>

// ---------------- constants ----------------
#define NN      50000
#define MAXE    2000000
#define HEADS   4
#define HC      256          // HEADS*HID
#define OUTC    128
#define KDIM    256          // all GEMMs have K=256
#define NB_SCAN ((NN + 255) / 256)

// ---------------- device scratch ----------------
__device__ float    g_proj[(size_t)NN * HC];
__device__ float    g_h0  [(size_t)NN * HC];
__device__ float    g_als [NN * HEADS];
__device__ float    g_ald [NN * HEADS];
__device__ int      g_src [MAXE];
__device__ int      g_dst [MAXE];
__device__ int      g_ssrc[MAXE];
__device__ int      g_cnt [NN];
__device__ int      g_tmp [NN];
__device__ int      g_bsum[256];
__device__ int      g_boff[256];
__device__ int      g_cursor[NN];
__device__ int      g_rowptr[NN + 1];
__device__ int      g_is64;
__device__ __nv_bfloat16 g_ahi[(size_t)NN * KDIM];
__device__ __nv_bfloat16 g_alo[(size_t)NN * KDIM];
__device__ __nv_bfloat16 g_w0hi[KDIM * HC],  g_w0lo[KDIM * HC];
__device__ __nv_bfloat16 g_w1hi[KDIM * HC],  g_w1lo[KDIM * HC];
__device__ __nv_bfloat16 g_wchi[KDIM * 256], g_wclo[KDIM * 256];  // [W2 | Wl]

// ---------------- helpers ----------------
__device__ __forceinline__ float lrelu(float v) { return v > 0.f ? v : 0.2f * v; }

__device__ __forceinline__ uint32_t s2u(const void* p) {
    uint32_t a;
    asm("{ .reg .u64 t; cvta.to.shared.u64 t, %1; cvt.u32.u64 %0, t; }" : "=r"(a) : "l"(p));
    return a;
}

__device__ __forceinline__ void cpa16(uint32_t dst, const void* src, int ssize) {
    asm volatile("cp.async.cg.shared.global [%0], [%1], 16, %2;"
                 :: "r"(dst), "l"(src), "r"(ssize));
}

#define LDM4(d, addr) \
    asm volatile("ldmatrix.sync.aligned.m8n8.x4.shared.b16 {%0,%1,%2,%3}, [%4];" \
        : "=r"((d)[0]), "=r"((d)[1]), "=r"((d)[2]), "=r"((d)[3]) : "r"(addr))

#define MMA_BF16(c, a, b0, b1) \
    asm volatile("mma.sync.aligned.m16n8k16.row.col.f32.bf16.bf16.f32 " \
        "{%0,%1,%2,%3}, {%4,%5,%6,%7}, {%8,%9}, {%0,%1,%2,%3};" \
        : "+f"((c)[0]), "+f"((c)[1]), "+f"((c)[2]), "+f"((c)[3]) \
        : "r"((a)[0]), "r"((a)[1]), "r"((a)[2]), "r"((a)[3]), "r"(b0), "r"(b1))

// ---------------- edge index prep ----------------
__global__ void probe_kernel(const int* p32, int nchk) {
    __shared__ int cnt;
    if (threadIdx.x == 0) cnt = 0;
    __syncthreads();
    int z = 0;
    for (int k = threadIdx.x; k < nchk; k += 256)
        if (p32[2 * k + 1] == 0) z++;
    atomicAdd(&cnt, z);
    __syncthreads();
    if (threadIdx.x == 0) g_is64 = (cnt * 2 > nchk) ? 1 : 0;
}

__global__ void convert_hist(const void* ei, int E) {
    int e = blockIdx.x * blockDim.x + threadIdx.x;
    if (e >= E || e >= MAXE) return;
    int s, d;
    if (g_is64) {
        const long long* p = (const long long*)ei;
        s = (int)p[e];
        d = (int)p[(size_t)E + e];
    } else {
        const int* p = (const int*)ei;
        s = p[e];
        d = p[E + e];
    }
    g_src[e] = s;
    g_dst[e] = d;
    atomicAdd(&g_cnt[d], 1);
}

// ---------------- 3-phase exclusive scan ----------------
__global__ void scanA() {
    int i = blockIdx.x * 256 + threadIdx.x;
    int lane = threadIdx.x & 31, warp = threadIdx.x >> 5;
    int v = (i < NN) ? g_cnt[i] : 0;
    int x = v;
#pragma unroll
    for (int off = 1; off < 32; off <<= 1) {
        int t = __shfl_up_sync(0xffffffffu, x, off);
        if (lane >= off) x += t;
    }
    __shared__ int ws[8];
    if (lane == 31) ws[warp] = x;
    __syncthreads();
    if (threadIdx.x == 0) {
        int run = 0;
#pragma unroll
        for (int j = 0; j < 8; j++) { int t = ws[j]; ws[j] = run; run += t; }
        g_bsum[blockIdx.x] = run;
    }
    __syncthreads();
    if (i < NN) g_tmp[i] = x - v + ws[warp];
}

__global__ void scanB(int nb) {
    int tid = threadIdx.x, lane = tid & 31, warp = tid >> 5;
    int v = (tid < nb) ? g_bsum[tid] : 0;
    int x = v;
#pragma unroll
    for (int off = 1; off < 32; off <<= 1) {
        int t = __shfl_up_sync(0xffffffffu, x, off);
        if (lane >= off) x += t;
    }
    __shared__ int ws[8];
    if (lane == 31) ws[warp] = x;
    __syncthreads();
    if (tid == 0) {
        int run = 0;
#pragma unroll
        for (int j = 0; j < 8; j++) { int t = ws[j]; ws[j] = run; run += t; }
        g_rowptr[NN] = run;
    }
    __syncthreads();
    g_boff[tid] = x - v + ws[warp];
}

__global__ void scanC() {
    int i = blockIdx.x * 256 + threadIdx.x;
    if (i < NN) {
        int r = g_tmp[i] + g_boff[blockIdx.x];
        g_rowptr[i] = r;
        g_cursor[i] = r;
    }
}

__global__ void scatter_kernel(int E) {
    int e = blockIdx.x * blockDim.x + threadIdx.x;
    if (e >= E || e >= MAXE) return;
    int pos = atomicAdd(&g_cursor[g_dst[e]], 1);
    g_ssrc[pos] = g_src[e];
}

// ---------------- bf16 hi/lo split (layer-0 input only) ----------------
__global__ void split_act(const float* __restrict__ in, __nv_bfloat16* __restrict__ hi,
                          __nv_bfloat16* __restrict__ lo, int total4) {
    int i = blockIdx.x * blockDim.x + threadIdx.x;
    if (i >= total4) return;
    float4 v = ((const float4*)in)[i];
    float vv[4] = {v.x, v.y, v.z, v.w};
    __nv_bfloat16 h[4], l[4];
#pragma unroll
    for (int j = 0; j < 4; j++) {
        h[j] = __float2bfloat16(vv[j]);
        l[j] = __float2bfloat16(vv[j] - __bfloat162float(h[j]));
    }
    ((__nv_bfloat162*)hi)[2 * i]     = __nv_bfloat162(h[0], h[1]);
    ((__nv_bfloat162*)hi)[2 * i + 1] = __nv_bfloat162(h[2], h[3]);
    ((__nv_bfloat162*)lo)[2 * i]     = __nv_bfloat162(l[0], l[1]);
    ((__nv_bfloat162*)lo)[2 * i + 1] = __nv_bfloat162(l[2], l[3]);
}

// ---------------- weight transpose + split ----------------
__global__ void wsplit(const float* __restrict__ W, int Nn,
                       __nv_bfloat16* __restrict__ hi, __nv_bfloat16* __restrict__ lo) {
    int idx = blockIdx.x * blockDim.x + threadIdx.x;
    if (idx >= Nn * KDIM) return;
    int n = idx >> 8, k = idx & 255;
    float v = W[(size_t)k * Nn + n];
    __nv_bfloat16 h = __float2bfloat16(v);
    hi[idx] = h;
    lo[idx] = __float2bfloat16(v - __bfloat162float(h));
}

// ---------------- HMMA split-bf16 GEMM, 2-stage cp.async pipeline ----------------
// Per-stage smem layout: A_HI 0, A_LO 14336, B_HI 28672, B_LO 35840; stage stride 43008.
// Reduction scratch for fused logits at 86016 (2 x 128 floats).
#define STG 43008
__global__ void __launch_bounds__(256, 2) gemm_mma(
    const __nv_bfloat16* __restrict__ Ahi, const __nv_bfloat16* __restrict__ Alo,
    const __nv_bfloat16* __restrict__ Bhi, const __nv_bfloat16* __restrict__ Blo,
    float* __restrict__ C, int M, int Nn,
    int lmode, const float* __restrict__ a_s, const float* __restrict__ a_d,
    float* __restrict__ als, float* __restrict__ ald)
{
    extern __shared__ __align__(16) char smem[];
    float* red_ss = (float*)(smem + 2 * STG);
    float* red_sd = red_ss + 128;
    constexpr int A_HI = 0;
    constexpr int A_LO = 14336;
    constexpr int B_HI = 28672;
    constexpr int B_LO = 35840;

    const int tid  = threadIdx.x;
    const int lane = tid & 31;
    const int wid  = tid >> 5;
    const int warpRow = wid & 3;
    const int warpCol = wid >> 2;
    const int rowBase = blockIdx.x * 128;
    const int colBase = blockIdx.y * 64;

    float acc[2][4][4];
#pragma unroll
    for (int i = 0; i < 2; i++)
#pragma unroll
        for (int j = 0; j < 4; j++)
#pragma unroll
            for (int q = 0; q < 4; q++) acc[i][j][q] = 0.f;

    const uint32_t sb = s2u(smem);
    uint32_t aAdrH[2], aAdrL[2];
#pragma unroll
    for (int m16 = 0; m16 < 2; m16++) {
        uint32_t r = warpRow * 32 + m16 * 16 + (lane & 15);
        uint32_t cb = ((lane >> 4) * 8) * 2;
        aAdrH[m16] = sb + A_HI + r * 112 + cb;
        aAdrL[m16] = sb + A_LO + r * 112 + cb;
    }
    uint32_t bAdrH[2], bAdrL[2];
#pragma unroll
    for (int nbp = 0; nbp < 2; nbp++) {
        uint32_t r = warpCol * 32 + nbp * 16 + ((lane >> 4) << 3) + (lane & 7);
        uint32_t cb = (((lane >> 3) & 1) * 8) * 2;
        bAdrH[nbp] = sb + B_HI + r * 112 + cb;
        bAdrL[nbp] = sb + B_LO + r * 112 + cb;
    }

    // per-thread cp.async source/dst indices
    const int ar0 = tid >> 2, aseg = tid & 3;                // A: rows tid>>2 and +64
    const int br0 = tid >> 2;                                 // B: row tid>>2

    auto prefetch = [&](int c) {
        const uint32_t base = sb + (uint32_t)(c & 1) * STG;
        const int k0 = c * 32;
#pragma unroll
        for (int it = 0; it < 2; it++) {
            int r = ar0 + it * 64;
            int gr = rowBase + r;
            int ok = (gr < M) ? 16 : 0;
            size_t g = (size_t)(ok ? gr : 0) * KDIM + k0 + aseg * 8;
            cpa16(base + A_HI + r * 112 + aseg * 16, Ahi + g, ok);
            cpa16(base + A_LO + r * 112 + aseg * 16, Alo + g, ok);
        }
        {
            size_t g = (size_t)(colBase + br0) * KDIM + k0 + aseg * 8;
            cpa16(base + B_HI + br0 * 112 + aseg * 16, Bhi + g, 16);
            cpa16(base + B_LO + br0 * 112 + aseg * 16, Blo + g, 16);
        }
        asm volatile("cp.async.commit_group;");
    };

    prefetch(0);
    for (int c = 0; c < 8; c++) {
        if (c < 7) {
            prefetch(c + 1);
            asm volatile("cp.async.wait_group 1;");
        } else {
            asm volatile("cp.async.wait_group 0;");
        }
        __syncthreads();
        const uint32_t so = (uint32_t)(c & 1) * STG;
#pragma unroll
        for (int kk = 0; kk < 2; kk++) {
            const uint32_t kb = so + kk * 32;
            uint32_t ah[2][4], al[2][4], bh[2][4], bl[2][4];
            LDM4(ah[0], aAdrH[0] + kb);
            LDM4(ah[1], aAdrH[1] + kb);
            LDM4(al[0], aAdrL[0] + kb);
            LDM4(al[1], aAdrL[1] + kb);
            LDM4(bh[0], bAdrH[0] + kb);
            LDM4(bh[1], bAdrH[1] + kb);
            LDM4(bl[0], bAdrL[0] + kb);
            LDM4(bl[1], bAdrL[1] + kb);
#pragma unroll
            for (int m16 = 0; m16 < 2; m16++) {
#pragma unroll
                for (int nb = 0; nb < 4; nb++) {
                    const int p = nb >> 1, q = (nb & 1) * 2;
                    MMA_BF16(acc[m16][nb], ah[m16], bh[p][q], bh[p][q + 1]);
                    MMA_BF16(acc[m16][nb], ah[m16], bl[p][q], bl[p][q + 1]);
                    MMA_BF16(acc[m16][nb], al[m16], bh[p][q], bh[p][q + 1]);
                }
            }
        }
        __syncthreads();
    }

    // ---- store C ----
#pragma unroll
    for (int m16 = 0; m16 < 2; m16++) {
        int r0 = rowBase + warpRow * 32 + m16 * 16 + (lane >> 2);
#pragma unroll
        for (int nb = 0; nb < 4; nb++) {
            int col = colBase + warpCol * 32 + nb * 8 + (lane & 3) * 2;
            if (r0 < M)
                *(float2*)(C + (size_t)r0 * Nn + col) =
                    make_float2(acc[m16][nb][0], acc[m16][nb][1]);
            if (r0 + 8 < M)
                *(float2*)(C + (size_t)(r0 + 8) * Nn + col) =
                    make_float2(acc[m16][nb][2], acc[m16][nb][3]);
        }
    }

    // ---- fused attention logits ----
    if (lmode == 1 || (lmode == 2 && blockIdx.y < 2)) {
        const int y = blockIdx.y;
        float pss[2][2] = {{0.f, 0.f}, {0.f, 0.f}};
        float psd[2][2] = {{0.f, 0.f}, {0.f, 0.f}};
#pragma unroll
        for (int m16 = 0; m16 < 2; m16++) {
#pragma unroll
            for (int nb = 0; nb < 4; nb++) {
                int cl = warpCol * 32 + nb * 8 + (lane & 3) * 2;
                float s0 = __ldg(a_s + y * 64 + cl), s1 = __ldg(a_s + y * 64 + cl + 1);
                float d0 = __ldg(a_d + y * 64 + cl), d1 = __ldg(a_d + y * 64 + cl + 1);
                pss[m16][0] += acc[m16][nb][0] * s0 + acc[m16][nb][1] * s1;
                psd[m16][0] += acc[m16][nb][0] * d0 + acc[m16][nb][1] * d1;
                pss[m16][1] += acc[m16][nb][2] * s0 + acc[m16][nb][3] * s1;
                psd[m16][1] += acc[m16][nb][2] * d0 + acc[m16][nb][3] * d1;
            }
        }
#pragma unroll
        for (int m16 = 0; m16 < 2; m16++)
#pragma unroll
            for (int hh = 0; hh < 2; hh++) {
                pss[m16][hh] += __shfl_xor_sync(0xffffffffu, pss[m16][hh], 1);
                pss[m16][hh] += __shfl_xor_sync(0xffffffffu, pss[m16][hh], 2);
                psd[m16][hh] += __shfl_xor_sync(0xffffffffu, psd[m16][hh], 1);
                psd[m16][hh] += __shfl_xor_sync(0xffffffffu, psd[m16][hh], 2);
            }
        if (warpCol == 0 && (lane & 3) == 0) {
#pragma unroll
            for (int m16 = 0; m16 < 2; m16++)
#pragma unroll
                for (int hh = 0; hh < 2; hh++) {
                    int rb = warpRow * 32 + m16 * 16 + hh * 8 + (lane >> 2);
                    red_ss[rb] = pss[m16][hh];
                    red_sd[rb] = psd[m16][hh];
                }
        }
        __syncthreads();
        if (warpCol == 1 && (lane & 3) == 0) {
#pragma unroll
            for (int m16 = 0; m16 < 2; m16++)
#pragma unroll
                for (int hh = 0; hh < 2; hh++) {
                    int rb = warpRow * 32 + m16 * 16 + hh * 8 + (lane >> 2);
                    int row = rowBase + rb;
                    if (row < M) {
                        float S = red_ss[rb] + pss[m16][hh];
                        float D = red_sd[rb] + psd[m16][hh];
                        if (lmode == 1) {
                            als[row * 4 + y] = S;
                            ald[row * 4 + y] = D;
                        } else {
                            atomicAdd(&als[row], S);
                            atomicAdd(&ald[row], D);
                        }
                    }
                }
        }
    }
}

// ---------------- fused CSR aggregation, H=4, 256 ch: warp per dst ----------------
__global__ void gat_agg256(const float* __restrict__ proj,
                           const float* __restrict__ als, const float* __restrict__ ald,
                           const float* __restrict__ bias, const float* __restrict__ res,
                           float* __restrict__ outp,
                           __nv_bfloat16* __restrict__ hi, __nv_bfloat16* __restrict__ lo) {
    int w = (blockIdx.x * blockDim.x + threadIdx.x) >> 5;
    if (w >= NN) return;
    const int lane = threadIdx.x & 31;
    const int d = w;
    const float aldl = (lane < 4) ? ald[d * 4 + lane] : 0.f;

    float wt = 0.f, sden = 0.f;
    if (lane < 4) {
        wt = __expf(lrelu(als[d * 4 + lane] + aldl));
        sden = wt;
    }
    float wh = __shfl_sync(0xffffffffu, wt, lane >> 3);

    const float4* pr = (const float4*)proj;
    float4 a0, a1;
    {
        float4 p0 = pr[(size_t)d * 64 + lane * 2];
        float4 p1 = pr[(size_t)d * 64 + lane * 2 + 1];
        a0 = make_float4(wh * p0.x, wh * p0.y, wh * p0.z, wh * p0.w);
        a1 = make_float4(wh * p1.x, wh * p1.y, wh * p1.z, wh * p1.w);
    }
    const int jb = g_rowptr[d], je = g_rowptr[d + 1];
    int s = (jb < je) ? g_ssrc[jb] : 0;
    for (int j = jb; j < je; j++) {
        int sn = (j + 1 < je) ? g_ssrc[j + 1] : 0;
        float w2 = 0.f;
        if (lane < 4) {
            w2 = __expf(lrelu(als[s * 4 + lane] + aldl));
            sden += w2;
        }
        float wh2 = __shfl_sync(0xffffffffu, w2, lane >> 3);
        float4 p0 = pr[(size_t)s * 64 + lane * 2];
        float4 p1 = pr[(size_t)s * 64 + lane * 2 + 1];
        a0.x = fmaf(wh2, p0.x, a0.x); a0.y = fmaf(wh2, p0.y, a0.y);
        a0.z = fmaf(wh2, p0.z, a0.z); a0.w = fmaf(wh2, p0.w, a0.w);
        a1.x = fmaf(wh2, p1.x, a1.x); a1.y = fmaf(wh2, p1.y, a1.y);
        a1.z = fmaf(wh2, p1.z, a1.z); a1.w = fmaf(wh2, p1.w, a1.w);
        s = sn;
    }
    float inv = 1.0f / __shfl_sync(0xffffffffu, sden, lane >> 3);
    float4 b0 = ((const float4*)bias)[lane * 2];
    float4 b1 = ((const float4*)bias)[lane * 2 + 1];
    float o[8];
    o[0] = a0.x * inv + b0.x; o[1] = a0.y * inv + b0.y;
    o[2] = a0.z * inv + b0.z; o[3] = a0.w * inv + b0.w;
    o[4] = a1.x * inv + b1.x; o[5] = a1.y * inv + b1.y;
    o[6] = a1.z * inv + b1.z; o[7] = a1.w * inv + b1.w;
    if (res) {
        float4 r0 = ((const float4*)res)[(size_t)d * 64 + lane * 2];
        float4 r1 = ((const float4*)res)[(size_t)d * 64 + lane * 2 + 1];
        o[0] += r0.x; o[1] += r0.y; o[2] += r0.z; o[3] += r0.w;
        o[4] += r1.x; o[5] += r1.y; o[6] += r1.z; o[7] += r1.w;
    }
    if (outp) {
        ((float4*)outp)[(size_t)d * 64 + lane * 2] = make_float4(o[0], o[1], o[2], o[3]);
        ((float4*)outp)[(size_t)d * 64 + lane * 2 + 1] = make_float4(o[4], o[5], o[6], o[7]);
    }
    __nv_bfloat162 hv[4], lv[4];
#pragma unroll
    for (int q = 0; q < 4; q++) {
        __nv_bfloat16 h0b = __float2bfloat16(o[2 * q]);
        __nv_bfloat16 h1b = __float2bfloat16(o[2 * q + 1]);
        hv[q] = __nv_bfloat162(h0b, h1b);
        lv[q] = __nv_bfloat162(__float2bfloat16(o[2 * q] - __bfloat162float(h0b)),
                               __float2bfloat16(o[2 * q + 1] - __bfloat162float(h1b)));
    }
    *(uint4*)(hi + (size_t)d * 256 + lane * 8) = *(uint4*)hv;
    *(uint4*)(lo + (size_t)d * 256 + lane * 8) = *(uint4*)lv;
}

// ---------------- fused CSR aggregation, H=1, 128 ch (layer 2) ----------------
__global__ void gat_agg128(const float* __restrict__ proj,
                           const float* __restrict__ als, const float* __restrict__ ald,
                           const float* __restrict__ bias, const float* __restrict__ bias2,
                           float* __restrict__ outp) {
    int w = (blockIdx.x * blockDim.x + threadIdx.x) >> 5;
    if (w >= NN) return;
    const int lane = threadIdx.x & 31;
    const int d = w;
    const float aldv = __shfl_sync(0xffffffffu, (lane == 0) ? ald[d] : 0.f, 0);

    float wt = 0.f, sden = 0.f;
    if (lane == 0) {
        wt = __expf(lrelu(als[d] + aldv));
        sden = wt;
    }
    float wh = __shfl_sync(0xffffffffu, wt, 0);
    const float4* pr = (const float4*)proj;
    float4 a0;
    {
        float4 p = pr[(size_t)d * 64 + lane];
        a0 = make_float4(wh * p.x, wh * p.y, wh * p.z, wh * p.w);
    }
    const int jb = g_rowptr[d], je = g_rowptr[d + 1];
    int s = (jb < je) ? g_ssrc[jb] : 0;
    for (int j = jb; j < je; j++) {
        int sn = (j + 1 < je) ? g_ssrc[j + 1] : 0;
        float w2 = 0.f;
        if (lane == 0) {
            w2 = __expf(lrelu(als[s] + aldv));
            sden += w2;
        }
        float wh2 = __shfl_sync(0xffffffffu, w2, 0);
        float4 p = pr[(size_t)s * 64 + lane];
        a0.x = fmaf(wh2, p.x, a0.x); a0.y = fmaf(wh2, p.y, a0.y);
        a0.z = fmaf(wh2, p.z, a0.z); a0.w = fmaf(wh2, p.w, a0.w);
        s = sn;
    }
    float inv = 1.0f / __shfl_sync(0xffffffffu, sden, 0);
    float4 b0 = ((const float4*)bias)[lane];
    float4 b2 = ((const float4*)bias2)[lane];
    float4 l0 = pr[(size_t)d * 64 + 32 + lane];
    float4 o = make_float4(a0.x * inv + b0.x + b2.x + l0.x,
                           a0.y * inv + b0.y + b2.y + l0.y,
                           a0.z * inv + b0.z + b2.z + l0.z,
                           a0.w * inv + b0.w + b2.w + l0.w);
    ((float4*)outp)[(size_t)d * 32 + lane] = o;
}

// ---------------- host orchestration ----------------
extern "C" void kernel_launch(void* const* d_in, const int* in_sizes, int n_in,
                              void* d_out, int out_size) {
    const float* x   = (const float*)d_in[0];
    const void*  ei  = d_in[1];
    const float* W0  = (const float*)d_in[2];
    const float* as0 = (const float*)d_in[3];
    const float* ad0 = (const float*)d_in[4];
    const float* b0  = (const float*)d_in[5];
    const float* W1  = (const float*)d_in[6];
    const float* as1 = (const float*)d_in[7];
    const float* ad1 = (const float*)d_in[8];
    const float* b1  = (const float*)d_in[9];
    const float* W2  = (const float*)d_in[10];
    const float* as2 = (const float*)d_in[11];
    const float* ad2 = (const float*)d_in[12];
    const float* b2  = (const float*)d_in[13];
    const float* Wl  = (const float*)d_in[14];
    const float* bl  = (const float*)d_in[15];
    float* out = (float*)d_out;
    const int E = in_sizes[1] / 2;

    float *p_proj, *p_h0, *p_als, *p_ald;
    int *p_cnt;
    __nv_bfloat16 *p_ahi, *p_alo, *p_w0hi, *p_w0lo, *p_w1hi, *p_w1lo, *p_wchi, *p_wclo;
    cudaGetSymbolAddress((void**)&p_proj, g_proj);
    cudaGetSymbolAddress((void**)&p_h0,   g_h0);
    cudaGetSymbolAddress((void**)&p_als,  g_als);
    cudaGetSymbolAddress((void**)&p_ald,  g_ald);
    cudaGetSymbolAddress((void**)&p_cnt,  g_cnt);
    cudaGetSymbolAddress((void**)&p_ahi,  g_ahi);
    cudaGetSymbolAddress((void**)&p_alo,  g_alo);
    cudaGetSymbolAddress((void**)&p_w0hi, g_w0hi);
    cudaGetSymbolAddress((void**)&p_w0lo, g_w0lo);
    cudaGetSymbolAddress((void**)&p_w1hi, g_w1hi);
    cudaGetSymbolAddress((void**)&p_w1lo, g_w1lo);
    cudaGetSymbolAddress((void**)&p_wchi, g_wchi);
    cudaGetSymbolAddress((void**)&p_wclo, g_wclo);

    constexpr int GEMM_SMEM = 2 * STG + 1024;   // 87040
    cudaFuncSetAttribute((const void*)gemm_mma,
                         cudaFuncAttributeMaxDynamicSharedMemorySize, GEMM_SMEM);

    // ---- CSR build ----
    probe_kernel<<<1, 256>>>((const int*)ei, E > 4096 ? 4096 : E);
    cudaMemsetAsync(p_cnt, 0, NN * sizeof(int));
    convert_hist<<<(E + 255) / 256, 256>>>(ei, E);
    scanA<<<NB_SCAN, 256>>>();
    scanB<<<1, 256>>>(NB_SCAN);
    scanC<<<NB_SCAN, 256>>>();
    scatter_kernel<<<(E + 255) / 256, 256>>>(E);

    // ---- weight prep ----
    wsplit<<<(HC * KDIM + 255) / 256, 256>>>(W0, HC, p_w0hi, p_w0lo);
    wsplit<<<(HC * KDIM + 255) / 256, 256>>>(W1, HC, p_w1hi, p_w1lo);
    wsplit<<<(OUTC * KDIM + 255) / 256, 256>>>(W2, OUTC, p_wchi, p_wclo);
    wsplit<<<(OUTC * KDIM + 255) / 256, 256>>>(Wl, OUTC, p_wchi + (size_t)OUTC * KDIM,
                                               p_wclo + (size_t)OUTC * KDIM);

    const int GEMM_BX = (NN + 127) / 128;
    const int total4 = NN * KDIM / 4;
    const int AGG_BLKS = (NN * 32 + 255) / 256;

    // ---- layer 0 ----
    split_act<<<(total4 + 255) / 256, 256>>>(x, p_ahi, p_alo, total4);
    gemm_mma<<<dim3(GEMM_BX, 4), 256, GEMM_SMEM>>>(p_ahi, p_alo, p_w0hi, p_w0lo,
                                                   p_proj, NN, HC, 1, as0, ad0, p_als, p_ald);
    gat_agg256<<<AGG_BLKS, 256>>>(p_proj, p_als, p_ald, b0, nullptr, p_h0, p_ahi, p_alo);

    // ---- layer 1 ----
    gemm_mma<<<dim3(GEMM_BX, 4), 256, GEMM_SMEM>>>(p_ahi, p_alo, p_w1hi, p_w1lo,
                                                   p_proj, NN, HC, 1, as1, ad1, p_als, p_ald);
    gat_agg256<<<AGG_BLKS, 256>>>(p_proj, p_als, p_ald, b1, p_h0, nullptr, p_ahi, p_alo);

    // ---- layer 2 ----
    cudaMemsetAsync(p_als, 0, NN * sizeof(float));
    cudaMemsetAsync(p_ald, 0, NN * sizeof(float));
    gemm_mma<<<dim3(GEMM_BX, 4), 256, GEMM_SMEM>>>(p_ahi, p_alo, p_wchi, p_wclo,
                                                   p_proj, NN, 256, 2, as2, ad2, p_als, p_ald);
    gat_agg128<<<AGG_BLKS, 256>>>(p_proj, p_als, p_ald, b2, bl, out);
}

// round 10
// speedup vs baseline: 3.0459x; 1.0258x over previous
#include <cuda_runtime.h>
#include <cuda_bf16.h>
#include <cstdint>

// ---------------- constants ----------------
#define NN      50000
#define MAXE    2000000
#define HEADS   4
#define HC      256          // HEADS*HID
#define OUTC    128
#define KDIM    256          // all GEMMs have K=256
#define NB_SCAN ((NN + 255) / 256)

// ---------------- device scratch ----------------
__device__ float    g_proj[(size_t)NN * HC];
__device__ float    g_h0  [(size_t)NN * HC];
__device__ float    g_als [NN * HEADS];
__device__ float    g_ald [NN * HEADS];
__device__ int      g_src [MAXE];
__device__ int      g_dst [MAXE];
__device__ int      g_ssrc[MAXE];
__device__ int      g_cnt [NN];
__device__ int      g_tmp [NN];
__device__ int      g_bsum[256];
__device__ int      g_boff[256];
__device__ int      g_cursor[NN];
__device__ int      g_rowptr[NN + 1];
__device__ int      g_is64;
__device__ __nv_bfloat16 g_ahi[(size_t)NN * KDIM];
__device__ __nv_bfloat16 g_alo[(size_t)NN * KDIM];
__device__ __nv_bfloat16 g_w0hi[KDIM * HC],  g_w0lo[KDIM * HC];
__device__ __nv_bfloat16 g_w1hi[KDIM * HC],  g_w1lo[KDIM * HC];
__device__ __nv_bfloat16 g_wchi[KDIM * 256], g_wclo[KDIM * 256];  // [W2 | Wl]

// ---------------- helpers ----------------
__device__ __forceinline__ float lrelu(float v) { return v > 0.f ? v : 0.2f * v; }

__device__ __forceinline__ uint32_t s2u(const void* p) {
    uint32_t a;
    asm("{ .reg .u64 t; cvta.to.shared.u64 t, %1; cvt.u32.u64 %0, t; }" : "=r"(a) : "l"(p));
    return a;
}

__device__ __forceinline__ void cpa16(uint32_t dst, const void* src, int ssize) {
    asm volatile("cp.async.cg.shared.global [%0], [%1], 16, %2;"
                 :: "r"(dst), "l"(src), "r"(ssize));
}

#define LDM4(d, addr) \
    asm volatile("ldmatrix.sync.aligned.m8n8.x4.shared.b16 {%0,%1,%2,%3}, [%4];" \
        : "=r"((d)[0]), "=r"((d)[1]), "=r"((d)[2]), "=r"((d)[3]) : "r"(addr))

#define MMA_BF16(c, a, b0, b1) \
    asm volatile("mma.sync.aligned.m16n8k16.row.col.f32.bf16.bf16.f32 " \
        "{%0,%1,%2,%3}, {%4,%5,%6,%7}, {%8,%9}, {%0,%1,%2,%3};" \
        : "+f"((c)[0]), "+f"((c)[1]), "+f"((c)[2]), "+f"((c)[3]) \
        : "r"((a)[0]), "r"((a)[1]), "r"((a)[2]), "r"((a)[3]), "r"(b0), "r"(b1))

// ---------------- edge index prep ----------------
__global__ void probe_kernel(const int* p32, int nchk) {
    __shared__ int cnt;
    if (threadIdx.x == 0) cnt = 0;
    __syncthreads();
    int z = 0;
    for (int k = threadIdx.x; k < nchk; k += 256)
        if (p32[2 * k + 1] == 0) z++;
    atomicAdd(&cnt, z);
    __syncthreads();
    if (threadIdx.x == 0) g_is64 = (cnt * 2 > nchk) ? 1 : 0;
}

__global__ void convert_hist(const void* ei, int E) {
    int e = blockIdx.x * blockDim.x + threadIdx.x;
    if (e >= E || e >= MAXE) return;
    int s, d;
    if (g_is64) {
        const long long* p = (const long long*)ei;
        s = (int)p[e];
        d = (int)p[(size_t)E + e];
    } else {
        const int* p = (const int*)ei;
        s = p[e];
        d = p[E + e];
    }
    g_src[e] = s;
    g_dst[e] = d;
    atomicAdd(&g_cnt[d], 1);
}

// ---------------- 3-phase exclusive scan ----------------
__global__ void scanA() {
    int i = blockIdx.x * 256 + threadIdx.x;
    int lane = threadIdx.x & 31, warp = threadIdx.x >> 5;
    int v = (i < NN) ? g_cnt[i] : 0;
    int x = v;
#pragma unroll
    for (int off = 1; off < 32; off <<= 1) {
        int t = __shfl_up_sync(0xffffffffu, x, off);
        if (lane >= off) x += t;
    }
    __shared__ int ws[8];
    if (lane == 31) ws[warp] = x;
    __syncthreads();
    if (threadIdx.x == 0) {
        int run = 0;
#pragma unroll
        for (int j = 0; j < 8; j++) { int t = ws[j]; ws[j] = run; run += t; }
        g_bsum[blockIdx.x] = run;
    }
    __syncthreads();
    if (i < NN) g_tmp[i] = x - v + ws[warp];
}

__global__ void scanB(int nb) {
    int tid = threadIdx.x, lane = tid & 31, warp = tid >> 5;
    int v = (tid < nb) ? g_bsum[tid] : 0;
    int x = v;
#pragma unroll
    for (int off = 1; off < 32; off <<= 1) {
        int t = __shfl_up_sync(0xffffffffu, x, off);
        if (lane >= off) x += t;
    }
    __shared__ int ws[8];
    if (lane == 31) ws[warp] = x;
    __syncthreads();
    if (tid == 0) {
        int run = 0;
#pragma unroll
        for (int j = 0; j < 8; j++) { int t = ws[j]; ws[j] = run; run += t; }
        g_rowptr[NN] = run;
    }
    __syncthreads();
    g_boff[tid] = x - v + ws[warp];
}

__global__ void scanC() {
    int i = blockIdx.x * 256 + threadIdx.x;
    if (i < NN) {
        int r = g_tmp[i] + g_boff[blockIdx.x];
        g_rowptr[i] = r;
        g_cursor[i] = r;
    }
}

__global__ void scatter_kernel(int E) {
    int e = blockIdx.x * blockDim.x + threadIdx.x;
    if (e >= E || e >= MAXE) return;
    int pos = atomicAdd(&g_cursor[g_dst[e]], 1);
    g_ssrc[pos] = g_src[e];
}

// ---------------- bf16 hi/lo split (layer-0 input only) ----------------
__global__ void split_act(const float* __restrict__ in, __nv_bfloat16* __restrict__ hi,
                          __nv_bfloat16* __restrict__ lo, int total4) {
    int i = blockIdx.x * blockDim.x + threadIdx.x;
    if (i >= total4) return;
    float4 v = ((const float4*)in)[i];
    float vv[4] = {v.x, v.y, v.z, v.w};
    __nv_bfloat16 h[4], l[4];
#pragma unroll
    for (int j = 0; j < 4; j++) {
        h[j] = __float2bfloat16(vv[j]);
        l[j] = __float2bfloat16(vv[j] - __bfloat162float(h[j]));
    }
    ((__nv_bfloat162*)hi)[2 * i]     = __nv_bfloat162(h[0], h[1]);
    ((__nv_bfloat162*)hi)[2 * i + 1] = __nv_bfloat162(h[2], h[3]);
    ((__nv_bfloat162*)lo)[2 * i]     = __nv_bfloat162(l[0], l[1]);
    ((__nv_bfloat162*)lo)[2 * i + 1] = __nv_bfloat162(l[2], l[3]);
}

// ---------------- merged weight transpose + split (all 4 matrices, 1 launch) ------
// ranges (in n*256+k local index space):
//   [0, 65536)        W0 (Nn=256) -> g_w0hi/lo
//   [65536, 131072)   W1 (Nn=256) -> g_w1hi/lo
//   [131072, 163840)  W2 (Nn=128) -> g_wchi/lo
//   [163840, 196608)  Wl (Nn=128) -> g_wchi/lo + 128*256
__global__ void wsplit_all(const float* __restrict__ W0, const float* __restrict__ W1,
                           const float* __restrict__ W2, const float* __restrict__ Wl) {
    int idx = blockIdx.x * blockDim.x + threadIdx.x;
    if (idx >= 196608) return;
    const float* W;
    __nv_bfloat16 *hi, *lo;
    int local, Nn;
    if (idx < 65536)       { W = W0; hi = g_w0hi; lo = g_w0lo; local = idx; Nn = 256; }
    else if (idx < 131072) { W = W1; hi = g_w1hi; lo = g_w1lo; local = idx - 65536; Nn = 256; }
    else if (idx < 163840) { W = W2; hi = g_wchi; lo = g_wclo; local = idx - 131072; Nn = 128; }
    else                   { W = Wl; hi = g_wchi + 128 * 256; lo = g_wclo + 128 * 256;
                             local = idx - 163840; Nn = 128; }
    int n = local >> 8, k = local & 255;
    float v = W[(size_t)k * Nn + n];
    __nv_bfloat16 h = __float2bfloat16(v);
    hi[local] = h;
    lo[local] = __float2bfloat16(v - __bfloat162float(h));
}

// ---------------- HMMA split-bf16 GEMM, 2-stage cp.async pipeline ----------------
#define STG 43008
__global__ void __launch_bounds__(256, 2) gemm_mma(
    const __nv_bfloat16* __restrict__ Ahi, const __nv_bfloat16* __restrict__ Alo,
    const __nv_bfloat16* __restrict__ Bhi, const __nv_bfloat16* __restrict__ Blo,
    float* __restrict__ C, int M, int Nn,
    int lmode, const float* __restrict__ a_s, const float* __restrict__ a_d,
    float* __restrict__ als, float* __restrict__ ald)
{
    extern __shared__ __align__(16) char smem[];
    float* red_ss = (float*)(smem + 2 * STG);
    float* red_sd = red_ss + 128;
    constexpr int A_HI = 0;
    constexpr int A_LO = 14336;
    constexpr int B_HI = 28672;
    constexpr int B_LO = 35840;

    const int tid  = threadIdx.x;
    const int lane = tid & 31;
    const int wid  = tid >> 5;
    const int warpRow = wid & 3;
    const int warpCol = wid >> 2;
    const int rowBase = blockIdx.x * 128;
    const int colBase = blockIdx.y * 64;

    float acc[2][4][4];
#pragma unroll
    for (int i = 0; i < 2; i++)
#pragma unroll
        for (int j = 0; j < 4; j++)
#pragma unroll
            for (int q = 0; q < 4; q++) acc[i][j][q] = 0.f;

    const uint32_t sb = s2u(smem);
    uint32_t aAdrH[2], aAdrL[2];
#pragma unroll
    for (int m16 = 0; m16 < 2; m16++) {
        uint32_t r = warpRow * 32 + m16 * 16 + (lane & 15);
        uint32_t cb = ((lane >> 4) * 8) * 2;
        aAdrH[m16] = sb + A_HI + r * 112 + cb;
        aAdrL[m16] = sb + A_LO + r * 112 + cb;
    }
    uint32_t bAdrH[2], bAdrL[2];
#pragma unroll
    for (int nbp = 0; nbp < 2; nbp++) {
        uint32_t r = warpCol * 32 + nbp * 16 + ((lane >> 4) << 3) + (lane & 7);
        uint32_t cb = (((lane >> 3) & 1) * 8) * 2;
        bAdrH[nbp] = sb + B_HI + r * 112 + cb;
        bAdrL[nbp] = sb + B_LO + r * 112 + cb;
    }

    const int ar0 = tid >> 2, aseg = tid & 3;
    const int br0 = tid >> 2;

    auto prefetch = [&](int c) {
        const uint32_t base = sb + (uint32_t)(c & 1) * STG;
        const int k0 = c * 32;
#pragma unroll
        for (int it = 0; it < 2; it++) {
            int r = ar0 + it * 64;
            int gr = rowBase + r;
            int ok = (gr < M) ? 16 : 0;
            size_t g = (size_t)(ok ? gr : 0) * KDIM + k0 + aseg * 8;
            cpa16(base + A_HI + r * 112 + aseg * 16, Ahi + g, ok);
            cpa16(base + A_LO + r * 112 + aseg * 16, Alo + g, ok);
        }
        {
            size_t g = (size_t)(colBase + br0) * KDIM + k0 + aseg * 8;
            cpa16(base + B_HI + br0 * 112 + aseg * 16, Bhi + g, 16);
            cpa16(base + B_LO + br0 * 112 + aseg * 16, Blo + g, 16);
        }
        asm volatile("cp.async.commit_group;");
    };

    prefetch(0);
    for (int c = 0; c < 8; c++) {
        if (c < 7) {
            prefetch(c + 1);
            asm volatile("cp.async.wait_group 1;");
        } else {
            asm volatile("cp.async.wait_group 0;");
        }
        __syncthreads();
        const uint32_t so = (uint32_t)(c & 1) * STG;
#pragma unroll
        for (int kk = 0; kk < 2; kk++) {
            const uint32_t kb = so + kk * 32;
            uint32_t ah[2][4], al[2][4], bh[2][4], bl[2][4];
            LDM4(ah[0], aAdrH[0] + kb);
            LDM4(ah[1], aAdrH[1] + kb);
            LDM4(al[0], aAdrL[0] + kb);
            LDM4(al[1], aAdrL[1] + kb);
            LDM4(bh[0], bAdrH[0] + kb);
            LDM4(bh[1], bAdrH[1] + kb);
            LDM4(bl[0], bAdrL[0] + kb);
            LDM4(bl[1], bAdrL[1] + kb);
#pragma unroll
            for (int m16 = 0; m16 < 2; m16++) {
#pragma unroll
                for (int nb = 0; nb < 4; nb++) {
                    const int p = nb >> 1, q = (nb & 1) * 2;
                    MMA_BF16(acc[m16][nb], ah[m16], bh[p][q], bh[p][q + 1]);
                    MMA_BF16(acc[m16][nb], ah[m16], bl[p][q], bl[p][q + 1]);
                    MMA_BF16(acc[m16][nb], al[m16], bh[p][q], bh[p][q + 1]);
                }
            }
        }
        __syncthreads();
    }

    // ---- store C ----
#pragma unroll
    for (int m16 = 0; m16 < 2; m16++) {
        int r0 = rowBase + warpRow * 32 + m16 * 16 + (lane >> 2);
#pragma unroll
        for (int nb = 0; nb < 4; nb++) {
            int col = colBase + warpCol * 32 + nb * 8 + (lane & 3) * 2;
            if (r0 < M)
                *(float2*)(C + (size_t)r0 * Nn + col) =
                    make_float2(acc[m16][nb][0], acc[m16][nb][1]);
            if (r0 + 8 < M)
                *(float2*)(C + (size_t)(r0 + 8) * Nn + col) =
                    make_float2(acc[m16][nb][2], acc[m16][nb][3]);
        }
    }

    // ---- fused attention logits ----
    if (lmode == 1 || (lmode == 2 && blockIdx.y < 2)) {
        const int y = blockIdx.y;
        float pss[2][2] = {{0.f, 0.f}, {0.f, 0.f}};
        float psd[2][2] = {{0.f, 0.f}, {0.f, 0.f}};
#pragma unroll
        for (int m16 = 0; m16 < 2; m16++) {
#pragma unroll
            for (int nb = 0; nb < 4; nb++) {
                int cl = warpCol * 32 + nb * 8 + (lane & 3) * 2;
                float s0 = __ldg(a_s + y * 64 + cl), s1 = __ldg(a_s + y * 64 + cl + 1);
                float d0 = __ldg(a_d + y * 64 + cl), d1 = __ldg(a_d + y * 64 + cl + 1);
                pss[m16][0] += acc[m16][nb][0] * s0 + acc[m16][nb][1] * s1;
                psd[m16][0] += acc[m16][nb][0] * d0 + acc[m16][nb][1] * d1;
                pss[m16][1] += acc[m16][nb][2] * s0 + acc[m16][nb][3] * s1;
                psd[m16][1] += acc[m16][nb][2] * d0 + acc[m16][nb][3] * d1;
            }
        }
#pragma unroll
        for (int m16 = 0; m16 < 2; m16++)
#pragma unroll
            for (int hh = 0; hh < 2; hh++) {
                pss[m16][hh] += __shfl_xor_sync(0xffffffffu, pss[m16][hh], 1);
                pss[m16][hh] += __shfl_xor_sync(0xffffffffu, pss[m16][hh], 2);
                psd[m16][hh] += __shfl_xor_sync(0xffffffffu, psd[m16][hh], 1);
                psd[m16][hh] += __shfl_xor_sync(0xffffffffu, psd[m16][hh], 2);
            }
        if (warpCol == 0 && (lane & 3) == 0) {
#pragma unroll
            for (int m16 = 0; m16 < 2; m16++)
#pragma unroll
                for (int hh = 0; hh < 2; hh++) {
                    int rb = warpRow * 32 + m16 * 16 + hh * 8 + (lane >> 2);
                    red_ss[rb] = pss[m16][hh];
                    red_sd[rb] = psd[m16][hh];
                }
        }
        __syncthreads();
        if (warpCol == 1 && (lane & 3) == 0) {
#pragma unroll
            for (int m16 = 0; m16 < 2; m16++)
#pragma unroll
                for (int hh = 0; hh < 2; hh++) {
                    int rb = warpRow * 32 + m16 * 16 + hh * 8 + (lane >> 2);
                    int row = rowBase + rb;
                    if (row < M) {
                        float S = red_ss[rb] + pss[m16][hh];
                        float D = red_sd[rb] + psd[m16][hh];
                        if (lmode == 1) {
                            als[row * 4 + y] = S;
                            ald[row * 4 + y] = D;
                        } else {
                            atomicAdd(&als[row], S);
                            atomicAdd(&ald[row], D);
                        }
                    }
                }
        }
    }
}

// ---------------- fused CSR aggregation, H=4, 256 ch: warp per dst ----------------
__global__ void gat_agg256(const float* __restrict__ proj,
                           const float* __restrict__ als, const float* __restrict__ ald,
                           const float* __restrict__ bias, const float* __restrict__ res,
                           float* __restrict__ outp,
                           __nv_bfloat16* __restrict__ hi, __nv_bfloat16* __restrict__ lo) {
    int w = (blockIdx.x * blockDim.x + threadIdx.x) >> 5;
    if (w >= NN) return;
    const int lane = threadIdx.x & 31;
    const int d = w;
    const float aldl = (lane < 4) ? ald[d * 4 + lane] : 0.f;

    float wt = 0.f, sden = 0.f;
    if (lane < 4) {
        wt = __expf(lrelu(als[d * 4 + lane] + aldl));
        sden = wt;
    }
    float wh = __shfl_sync(0xffffffffu, wt, lane >> 3);

    const float4* pr = (const float4*)proj;
    float4 a0, a1;
    {
        float4 p0 = pr[(size_t)d * 64 + lane * 2];
        float4 p1 = pr[(size_t)d * 64 + lane * 2 + 1];
        a0 = make_float4(wh * p0.x, wh * p0.y, wh * p0.z, wh * p0.w);
        a1 = make_float4(wh * p1.x, wh * p1.y, wh * p1.z, wh * p1.w);
    }
    const int jb = g_rowptr[d], je = g_rowptr[d + 1];
    int s = (jb < je) ? g_ssrc[jb] : 0;
    for (int j = jb; j < je; j++) {
        int sn = (j + 1 < je) ? g_ssrc[j + 1] : 0;
        float w2 = 0.f;
        if (lane < 4) {
            w2 = __expf(lrelu(als[s * 4 + lane] + aldl));
            sden += w2;
        }
        float wh2 = __shfl_sync(0xffffffffu, w2, lane >> 3);
        float4 p0 = pr[(size_t)s * 64 + lane * 2];
        float4 p1 = pr[(size_t)s * 64 + lane * 2 + 1];
        a0.x = fmaf(wh2, p0.x, a0.x); a0.y = fmaf(wh2, p0.y, a0.y);
        a0.z = fmaf(wh2, p0.z, a0.z); a0.w = fmaf(wh2, p0.w, a0.w);
        a1.x = fmaf(wh2, p1.x, a1.x); a1.y = fmaf(wh2, p1.y, a1.y);
        a1.z = fmaf(wh2, p1.z, a1.z); a1.w = fmaf(wh2, p1.w, a1.w);
        s = sn;
    }
    float inv = 1.0f / __shfl_sync(0xffffffffu, sden, lane >> 3);
    float4 b0 = ((const float4*)bias)[lane * 2];
    float4 b1 = ((const float4*)bias)[lane * 2 + 1];
    float o[8];
    o[0] = a0.x * inv + b0.x; o[1] = a0.y * inv + b0.y;
    o[2] = a0.z * inv + b0.z; o[3] = a0.w * inv + b0.w;
    o[4] = a1.x * inv + b1.x; o[5] = a1.y * inv + b1.y;
    o[6] = a1.z * inv + b1.z; o[7] = a1.w * inv + b1.w;
    if (res) {
        float4 r0 = ((const float4*)res)[(size_t)d * 64 + lane * 2];
        float4 r1 = ((const float4*)res)[(size_t)d * 64 + lane * 2 + 1];
        o[0] += r0.x; o[1] += r0.y; o[2] += r0.z; o[3] += r0.w;
        o[4] += r1.x; o[5] += r1.y; o[6] += r1.z; o[7] += r1.w;
    }
    if (outp) {
        ((float4*)outp)[(size_t)d * 64 + lane * 2] = make_float4(o[0], o[1], o[2], o[3]);
        ((float4*)outp)[(size_t)d * 64 + lane * 2 + 1] = make_float4(o[4], o[5], o[6], o[7]);
    }
    __nv_bfloat162 hv[4], lv[4];
#pragma unroll
    for (int q = 0; q < 4; q++) {
        __nv_bfloat16 h0b = __float2bfloat16(o[2 * q]);
        __nv_bfloat16 h1b = __float2bfloat16(o[2 * q + 1]);
        hv[q] = __nv_bfloat162(h0b, h1b);
        lv[q] = __nv_bfloat162(__float2bfloat16(o[2 * q] - __bfloat162float(h0b)),
                               __float2bfloat16(o[2 * q + 1] - __bfloat162float(h1b)));
    }
    *(uint4*)(hi + (size_t)d * 256 + lane * 8) = *(uint4*)hv;
    *(uint4*)(lo + (size_t)d * 256 + lane * 8) = *(uint4*)lv;
}

// ---------------- fused CSR aggregation, H=1, 128 ch (layer 2) ----------------
__global__ void gat_agg128(const float* __restrict__ proj,
                           const float* __restrict__ als, const float* __restrict__ ald,
                           const float* __restrict__ bias, const float* __restrict__ bias2,
                           float* __restrict__ outp) {
    int w = (blockIdx.x * blockDim.x + threadIdx.x) >> 5;
    if (w >= NN) return;
    const int lane = threadIdx.x & 31;
    const int d = w;
    const float aldv = __shfl_sync(0xffffffffu, (lane == 0) ? ald[d] : 0.f, 0);

    float wt = 0.f, sden = 0.f;
    if (lane == 0) {
        wt = __expf(lrelu(als[d] + aldv));
        sden = wt;
    }
    float wh = __shfl_sync(0xffffffffu, wt, 0);
    const float4* pr = (const float4*)proj;
    float4 a0;
    {
        float4 p = pr[(size_t)d * 64 + lane];
        a0 = make_float4(wh * p.x, wh * p.y, wh * p.z, wh * p.w);
    }
    const int jb = g_rowptr[d], je = g_rowptr[d + 1];
    int s = (jb < je) ? g_ssrc[jb] : 0;
    for (int j = jb; j < je; j++) {
        int sn = (j + 1 < je) ? g_ssrc[j + 1] : 0;
        float w2 = 0.f;
        if (lane == 0) {
            w2 = __expf(lrelu(als[s] + aldv));
            sden += w2;
        }
        float wh2 = __shfl_sync(0xffffffffu, w2, 0);
        float4 p = pr[(size_t)s * 64 + lane];
        a0.x = fmaf(wh2, p.x, a0.x); a0.y = fmaf(wh2, p.y, a0.y);
        a0.z = fmaf(wh2, p.z, a0.z); a0.w = fmaf(wh2, p.w, a0.w);
        s = sn;
    }
    float inv = 1.0f / __shfl_sync(0xffffffffu, sden, 0);
    float4 b0 = ((const float4*)bias)[lane];
    float4 b2 = ((const float4*)bias2)[lane];
    float4 l0 = pr[(size_t)d * 64 + 32 + lane];
    float4 o = make_float4(a0.x * inv + b0.x + b2.x + l0.x,
                           a0.y * inv + b0.y + b2.y + l0.y,
                           a0.z * inv + b0.z + b2.z + l0.z,
                           a0.w * inv + b0.w + b2.w + l0.w);
    ((float4*)outp)[(size_t)d * 32 + lane] = o;
}

// ---------------- host orchestration ----------------
extern "C" void kernel_launch(void* const* d_in, const int* in_sizes, int n_in,
                              void* d_out, int out_size) {
    const float* x   = (const float*)d_in[0];
    const void*  ei  = d_in[1];
    const float* W0  = (const float*)d_in[2];
    const float* as0 = (const float*)d_in[3];
    const float* ad0 = (const float*)d_in[4];
    const float* b0  = (const float*)d_in[5];
    const float* W1  = (const float*)d_in[6];
    const float* as1 = (const float*)d_in[7];
    const float* ad1 = (const float*)d_in[8];
    const float* b1  = (const float*)d_in[9];
    const float* W2  = (const float*)d_in[10];
    const float* as2 = (const float*)d_in[11];
    const float* ad2 = (const float*)d_in[12];
    const float* b2  = (const float*)d_in[13];
    const float* Wl  = (const float*)d_in[14];
    const float* bl  = (const float*)d_in[15];
    float* out = (float*)d_out;
    const int E = in_sizes[1] / 2;

    float *p_proj, *p_h0, *p_als, *p_ald;
    int *p_cnt;
    __nv_bfloat16 *p_ahi, *p_alo, *p_w0hi, *p_w0lo, *p_w1hi, *p_w1lo, *p_wchi, *p_wclo;
    cudaGetSymbolAddress((void**)&p_proj, g_proj);
    cudaGetSymbolAddress((void**)&p_h0,   g_h0);
    cudaGetSymbolAddress((void**)&p_als,  g_als);
    cudaGetSymbolAddress((void**)&p_ald,  g_ald);
    cudaGetSymbolAddress((void**)&p_cnt,  g_cnt);
    cudaGetSymbolAddress((void**)&p_ahi,  g_ahi);
    cudaGetSymbolAddress((void**)&p_alo,  g_alo);
    cudaGetSymbolAddress((void**)&p_w0hi, g_w0hi);
    cudaGetSymbolAddress((void**)&p_w0lo, g_w0lo);
    cudaGetSymbolAddress((void**)&p_w1hi, g_w1hi);
    cudaGetSymbolAddress((void**)&p_w1lo, g_w1lo);
    cudaGetSymbolAddress((void**)&p_wchi, g_wchi);
    cudaGetSymbolAddress((void**)&p_wclo, g_wclo);

    constexpr int GEMM_SMEM = 2 * STG + 1024;   // 87040
    cudaFuncSetAttribute((const void*)gemm_mma,
                         cudaFuncAttributeMaxDynamicSharedMemorySize, GEMM_SMEM);

    // ---- fork: CSR build on side stream, overlapped with prep + layer-0 GEMM ----
    cudaStream_t sE;
    cudaStreamCreateWithFlags(&sE, cudaStreamNonBlocking);
    cudaEvent_t evFork, evCSR;
    cudaEventCreateWithFlags(&evFork, cudaEventDisableTiming);
    cudaEventCreateWithFlags(&evCSR,  cudaEventDisableTiming);

    cudaEventRecord(evFork, 0);
    cudaStreamWaitEvent(sE, evFork, 0);
    probe_kernel<<<1, 256, 0, sE>>>((const int*)ei, E > 4096 ? 4096 : E);
    cudaMemsetAsync(p_cnt, 0, NN * sizeof(int), sE);
    convert_hist<<<(E + 255) / 256, 256, 0, sE>>>(ei, E);
    scanA<<<NB_SCAN, 256, 0, sE>>>();
    scanB<<<1, 256, 0, sE>>>(NB_SCAN);
    scanC<<<NB_SCAN, 256, 0, sE>>>();
    scatter_kernel<<<(E + 255) / 256, 256, 0, sE>>>(E);
    cudaEventRecord(evCSR, sE);

    const int GEMM_BX = (NN + 127) / 128;
    const int total4 = NN * KDIM / 4;
    const int AGG_BLKS = (NN * 32 + 255) / 256;

    // ---- main stream: prep + layer-0 GEMM (independent of CSR) ----
    split_act<<<(total4 + 255) / 256, 256>>>(x, p_ahi, p_alo, total4);
    wsplit_all<<<768, 256>>>(W0, W1, W2, Wl);
    gemm_mma<<<dim3(GEMM_BX, 4), 256, GEMM_SMEM>>>(p_ahi, p_alo, p_w0hi, p_w0lo,
                                                   p_proj, NN, HC, 1, as0, ad0, p_als, p_ald);

    // ---- join: aggregation needs the CSR ----
    cudaStreamWaitEvent(0, evCSR, 0);
    gat_agg256<<<AGG_BLKS, 256>>>(p_proj, p_als, p_ald, b0, nullptr, p_h0, p_ahi, p_alo);

    // ---- layer 1 ----
    gemm_mma<<<dim3(GEMM_BX, 4), 256, GEMM_SMEM>>>(p_ahi, p_alo, p_w1hi, p_w1lo,
                                                   p_proj, NN, HC, 1, as1, ad1, p_als, p_ald);
    gat_agg256<<<AGG_BLKS, 256>>>(p_proj, p_als, p_ald, b1, p_h0, nullptr, p_ahi, p_alo);

    // ---- layer 2 ----
    cudaMemsetAsync(p_als, 0, NN * sizeof(float));
    cudaMemsetAsync(p_ald, 0, NN * sizeof(float));
    gemm_mma<<<dim3(GEMM_BX, 4), 256, GEMM_SMEM>>>(p_ahi, p_alo, p_wchi, p_wclo,
                                                   p_proj, NN, 256, 2, as2, ad2, p_als, p_ald);
    gat_agg128<<<AGG_BLKS, 256>>>(p_proj, p_als, p_ald, b2, bl, out);

    cudaEventDestroy(evFork);
    cudaEventDestroy(evCSR);
    cudaStreamDestroy(sE);
}

// round 11
// speedup vs baseline: 3.1452x; 1.0326x over previous
#include <cuda_runtime.h>
#include <cuda_bf16.h>
#include <cstdint>

// ---------------- constants ----------------
#define NN      50000
#define MAXE    2000000
#define HEADS   4
#define HC      256          // HEADS*HID
#define OUTC    128
#define KDIM    256
#define NB_SCAN ((NN + 255) / 256)
// half-split at a 128-row boundary
#define NH1     25088
#define NH2     (NN - NH1)        // 24912
#define BX1     (NH1 / 128)       // 196
#define BX2     ((NN + 127) / 128 - BX1)  // 195

// ---------------- device scratch ----------------
__device__ float    g_projA[(size_t)NN * HC];
__device__ float    g_projB[(size_t)NN * HC];
__device__ float    g_h0  [(size_t)NN * HC];
__device__ float    g_alsA[NN * HEADS], g_aldA[NN * HEADS];
__device__ float    g_alsB[NN * HEADS], g_aldB[NN * HEADS];
__device__ float    g_als2[NN],         g_ald2[NN];
__device__ int      g_src [MAXE];
__device__ int      g_dst [MAXE];
__device__ int      g_ssrc[MAXE];
__device__ int      g_cnt [NN];
__device__ int      g_tmp [NN];
__device__ int      g_bsum[256];
__device__ int      g_boff[256];
__device__ int      g_cursor[NN];
__device__ int      g_rowptr[NN + 1];
__device__ int      g_is64;
__device__ __nv_bfloat16 g_ahi[(size_t)NN * KDIM];
__device__ __nv_bfloat16 g_alo[(size_t)NN * KDIM];
__device__ __nv_bfloat16 g_w0hi[KDIM * HC],  g_w0lo[KDIM * HC];
__device__ __nv_bfloat16 g_w1hi[KDIM * HC],  g_w1lo[KDIM * HC];
__device__ __nv_bfloat16 g_wchi[KDIM * 256], g_wclo[KDIM * 256];  // [W2 | Wl]

// ---------------- helpers ----------------
__device__ __forceinline__ float lrelu(float v) { return v > 0.f ? v : 0.2f * v; }

__device__ __forceinline__ uint32_t s2u(const void* p) {
    uint32_t a;
    asm("{ .reg .u64 t; cvta.to.shared.u64 t, %1; cvt.u32.u64 %0, t; }" : "=r"(a) : "l"(p));
    return a;
}

__device__ __forceinline__ void cpa16(uint32_t dst, const void* src, int ssize) {
    asm volatile("cp.async.cg.shared.global [%0], [%1], 16, %2;"
                 :: "r"(dst), "l"(src), "r"(ssize));
}

#define LDM4(d, addr) \
    asm volatile("ldmatrix.sync.aligned.m8n8.x4.shared.b16 {%0,%1,%2,%3}, [%4];" \
        : "=r"((d)[0]), "=r"((d)[1]), "=r"((d)[2]), "=r"((d)[3]) : "r"(addr))

#define MMA_BF16(c, a, b0, b1) \
    asm volatile("mma.sync.aligned.m16n8k16.row.col.f32.bf16.bf16.f32 " \
        "{%0,%1,%2,%3}, {%4,%5,%6,%7}, {%8,%9}, {%0,%1,%2,%3};" \
        : "+f"((c)[0]), "+f"((c)[1]), "+f"((c)[2]), "+f"((c)[3]) \
        : "r"((a)[0]), "r"((a)[1]), "r"((a)[2]), "r"((a)[3]), "r"(b0), "r"(b1))

// ---------------- edge index prep ----------------
__global__ void probe_kernel(const int* p32, int nchk) {
    __shared__ int cnt;
    if (threadIdx.x == 0) cnt = 0;
    __syncthreads();
    int z = 0;
    for (int k = threadIdx.x; k < nchk; k += 256)
        if (p32[2 * k + 1] == 0) z++;
    atomicAdd(&cnt, z);
    __syncthreads();
    if (threadIdx.x == 0) g_is64 = (cnt * 2 > nchk) ? 1 : 0;
}

__global__ void convert_hist(const void* ei, int E) {
    int e = blockIdx.x * blockDim.x + threadIdx.x;
    if (e >= E || e >= MAXE) return;
    int s, d;
    if (g_is64) {
        const long long* p = (const long long*)ei;
        s = (int)p[e];
        d = (int)p[(size_t)E + e];
    } else {
        const int* p = (const int*)ei;
        s = p[e];
        d = p[E + e];
    }
    g_src[e] = s;
    g_dst[e] = d;
    atomicAdd(&g_cnt[d], 1);
}

// ---------------- 3-phase exclusive scan ----------------
__global__ void scanA() {
    int i = blockIdx.x * 256 + threadIdx.x;
    int lane = threadIdx.x & 31, warp = threadIdx.x >> 5;
    int v = (i < NN) ? g_cnt[i] : 0;
    int x = v;
#pragma unroll
    for (int off = 1; off < 32; off <<= 1) {
        int t = __shfl_up_sync(0xffffffffu, x, off);
        if (lane >= off) x += t;
    }
    __shared__ int ws[8];
    if (lane == 31) ws[warp] = x;
    __syncthreads();
    if (threadIdx.x == 0) {
        int run = 0;
#pragma unroll
        for (int j = 0; j < 8; j++) { int t = ws[j]; ws[j] = run; run += t; }
        g_bsum[blockIdx.x] = run;
    }
    __syncthreads();
    if (i < NN) g_tmp[i] = x - v + ws[warp];
}

__global__ void scanB(int nb) {
    int tid = threadIdx.x, lane = tid & 31, warp = tid >> 5;
    int v = (tid < nb) ? g_bsum[tid] : 0;
    int x = v;
#pragma unroll
    for (int off = 1; off < 32; off <<= 1) {
        int t = __shfl_up_sync(0xffffffffu, x, off);
        if (lane >= off) x += t;
    }
    __shared__ int ws[8];
    if (lane == 31) ws[warp] = x;
    __syncthreads();
    if (tid == 0) {
        int run = 0;
#pragma unroll
        for (int j = 0; j < 8; j++) { int t = ws[j]; ws[j] = run; run += t; }
        g_rowptr[NN] = run;
    }
    __syncthreads();
    g_boff[tid] = x - v + ws[warp];
}

__global__ void scanC() {
    int i = blockIdx.x * 256 + threadIdx.x;
    if (i < NN) {
        int r = g_tmp[i] + g_boff[blockIdx.x];
        g_rowptr[i] = r;
        g_cursor[i] = r;
    }
}

__global__ void scatter_kernel(int E) {
    int e = blockIdx.x * blockDim.x + threadIdx.x;
    if (e >= E || e >= MAXE) return;
    int pos = atomicAdd(&g_cursor[g_dst[e]], 1);
    g_ssrc[pos] = g_src[e];
}

// ---------------- bf16 hi/lo split (layer-0 input only) ----------------
__global__ void split_act(const float* __restrict__ in, __nv_bfloat16* __restrict__ hi,
                          __nv_bfloat16* __restrict__ lo, int total4) {
    int i = blockIdx.x * blockDim.x + threadIdx.x;
    if (i >= total4) return;
    float4 v = ((const float4*)in)[i];
    float vv[4] = {v.x, v.y, v.z, v.w};
    __nv_bfloat16 h[4], l[4];
#pragma unroll
    for (int j = 0; j < 4; j++) {
        h[j] = __float2bfloat16(vv[j]);
        l[j] = __float2bfloat16(vv[j] - __bfloat162float(h[j]));
    }
    ((__nv_bfloat162*)hi)[2 * i]     = __nv_bfloat162(h[0], h[1]);
    ((__nv_bfloat162*)hi)[2 * i + 1] = __nv_bfloat162(h[2], h[3]);
    ((__nv_bfloat162*)lo)[2 * i]     = __nv_bfloat162(l[0], l[1]);
    ((__nv_bfloat162*)lo)[2 * i + 1] = __nv_bfloat162(l[2], l[3]);
}

// ---------------- merged weight transpose + split ----------------
__global__ void wsplit_all(const float* __restrict__ W0, const float* __restrict__ W1,
                           const float* __restrict__ W2, const float* __restrict__ Wl) {
    int idx = blockIdx.x * blockDim.x + threadIdx.x;
    if (idx >= 196608) return;
    const float* W;
    __nv_bfloat16 *hi, *lo;
    int local, Nn;
    if (idx < 65536)       { W = W0; hi = g_w0hi; lo = g_w0lo; local = idx; Nn = 256; }
    else if (idx < 131072) { W = W1; hi = g_w1hi; lo = g_w1lo; local = idx - 65536; Nn = 256; }
    else if (idx < 163840) { W = W2; hi = g_wchi; lo = g_wclo; local = idx - 131072; Nn = 128; }
    else                   { W = Wl; hi = g_wchi + 128 * 256; lo = g_wclo + 128 * 256;
                             local = idx - 163840; Nn = 128; }
    int n = local >> 8, k = local & 255;
    float v = W[(size_t)k * Nn + n];
    __nv_bfloat16 h = __float2bfloat16(v);
    hi[local] = h;
    lo[local] = __float2bfloat16(v - __bfloat162float(h));
}

// ---------------- HMMA split-bf16 GEMM, 2-stage cp.async pipeline ----------------
#define STG 43008
__global__ void __launch_bounds__(256, 2) gemm_mma(
    const __nv_bfloat16* __restrict__ Ahi, const __nv_bfloat16* __restrict__ Alo,
    const __nv_bfloat16* __restrict__ Bhi, const __nv_bfloat16* __restrict__ Blo,
    float* __restrict__ C, int M, int Nn,
    int lmode, const float* __restrict__ a_s, const float* __restrict__ a_d,
    float* __restrict__ als, float* __restrict__ ald, int bx0)
{
    extern __shared__ __align__(16) char smem[];
    float* red_ss = (float*)(smem + 2 * STG);
    float* red_sd = red_ss + 128;
    constexpr int A_HI = 0;
    constexpr int A_LO = 14336;
    constexpr int B_HI = 28672;
    constexpr int B_LO = 35840;

    const int tid  = threadIdx.x;
    const int lane = tid & 31;
    const int wid  = tid >> 5;
    const int warpRow = wid & 3;
    const int warpCol = wid >> 2;
    const int rowBase = (blockIdx.x + bx0) * 128;
    const int colBase = blockIdx.y * 64;

    float acc[2][4][4];
#pragma unroll
    for (int i = 0; i < 2; i++)
#pragma unroll
        for (int j = 0; j < 4; j++)
#pragma unroll
            for (int q = 0; q < 4; q++) acc[i][j][q] = 0.f;

    const uint32_t sb = s2u(smem);
    uint32_t aAdrH[2], aAdrL[2];
#pragma unroll
    for (int m16 = 0; m16 < 2; m16++) {
        uint32_t r = warpRow * 32 + m16 * 16 + (lane & 15);
        uint32_t cb = ((lane >> 4) * 8) * 2;
        aAdrH[m16] = sb + A_HI + r * 112 + cb;
        aAdrL[m16] = sb + A_LO + r * 112 + cb;
    }
    uint32_t bAdrH[2], bAdrL[2];
#pragma unroll
    for (int nbp = 0; nbp < 2; nbp++) {
        uint32_t r = warpCol * 32 + nbp * 16 + ((lane >> 4) << 3) + (lane & 7);
        uint32_t cb = (((lane >> 3) & 1) * 8) * 2;
        bAdrH[nbp] = sb + B_HI + r * 112 + cb;
        bAdrL[nbp] = sb + B_LO + r * 112 + cb;
    }

    const int ar0 = tid >> 2, aseg = tid & 3;
    const int br0 = tid >> 2;

    auto prefetch = [&](int c) {
        const uint32_t base = sb + (uint32_t)(c & 1) * STG;
        const int k0 = c * 32;
#pragma unroll
        for (int it = 0; it < 2; it++) {
            int r = ar0 + it * 64;
            int gr = rowBase + r;
            int ok = (gr < M) ? 16 : 0;
            size_t g = (size_t)(ok ? gr : 0) * KDIM + k0 + aseg * 8;
            cpa16(base + A_HI + r * 112 + aseg * 16, Ahi + g, ok);
            cpa16(base + A_LO + r * 112 + aseg * 16, Alo + g, ok);
        }
        {
            size_t g = (size_t)(colBase + br0) * KDIM + k0 + aseg * 8;
            cpa16(base + B_HI + br0 * 112 + aseg * 16, Bhi + g, 16);
            cpa16(base + B_LO + br0 * 112 + aseg * 16, Blo + g, 16);
        }
        asm volatile("cp.async.commit_group;");
    };

    prefetch(0);
    for (int c = 0; c < 8; c++) {
        if (c < 7) {
            prefetch(c + 1);
            asm volatile("cp.async.wait_group 1;");
        } else {
            asm volatile("cp.async.wait_group 0;");
        }
        __syncthreads();
        const uint32_t so = (uint32_t)(c & 1) * STG;
#pragma unroll
        for (int kk = 0; kk < 2; kk++) {
            const uint32_t kb = so + kk * 32;
            uint32_t ah[2][4], al[2][4], bh[2][4], bl[2][4];
            LDM4(ah[0], aAdrH[0] + kb);
            LDM4(ah[1], aAdrH[1] + kb);
            LDM4(al[0], aAdrL[0] + kb);
            LDM4(al[1], aAdrL[1] + kb);
            LDM4(bh[0], bAdrH[0] + kb);
            LDM4(bh[1], bAdrH[1] + kb);
            LDM4(bl[0], bAdrL[0] + kb);
            LDM4(bl[1], bAdrL[1] + kb);
#pragma unroll
            for (int m16 = 0; m16 < 2; m16++) {
#pragma unroll
                for (int nb = 0; nb < 4; nb++) {
                    const int p = nb >> 1, q = (nb & 1) * 2;
                    MMA_BF16(acc[m16][nb], ah[m16], bh[p][q], bh[p][q + 1]);
                    MMA_BF16(acc[m16][nb], ah[m16], bl[p][q], bl[p][q + 1]);
                    MMA_BF16(acc[m16][nb], al[m16], bh[p][q], bh[p][q + 1]);
                }
            }
        }
        __syncthreads();
    }

    // ---- store C ----
#pragma unroll
    for (int m16 = 0; m16 < 2; m16++) {
        int r0 = rowBase + warpRow * 32 + m16 * 16 + (lane >> 2);
#pragma unroll
        for (int nb = 0; nb < 4; nb++) {
            int col = colBase + warpCol * 32 + nb * 8 + (lane & 3) * 2;
            if (r0 < M)
                *(float2*)(C + (size_t)r0 * Nn + col) =
                    make_float2(acc[m16][nb][0], acc[m16][nb][1]);
            if (r0 + 8 < M)
                *(float2*)(C + (size_t)(r0 + 8) * Nn + col) =
                    make_float2(acc[m16][nb][2], acc[m16][nb][3]);
        }
    }

    // ---- fused attention logits ----
    if (lmode == 1 || (lmode == 2 && blockIdx.y < 2)) {
        const int y = blockIdx.y;
        float pss[2][2] = {{0.f, 0.f}, {0.f, 0.f}};
        float psd[2][2] = {{0.f, 0.f}, {0.f, 0.f}};
#pragma unroll
        for (int m16 = 0; m16 < 2; m16++) {
#pragma unroll
            for (int nb = 0; nb < 4; nb++) {
                int cl = warpCol * 32 + nb * 8 + (lane & 3) * 2;
                float s0 = __ldg(a_s + y * 64 + cl), s1 = __ldg(a_s + y * 64 + cl + 1);
                float d0 = __ldg(a_d + y * 64 + cl), d1 = __ldg(a_d + y * 64 + cl + 1);
                pss[m16][0] += acc[m16][nb][0] * s0 + acc[m16][nb][1] * s1;
                psd[m16][0] += acc[m16][nb][0] * d0 + acc[m16][nb][1] * d1;
                pss[m16][1] += acc[m16][nb][2] * s0 + acc[m16][nb][3] * s1;
                psd[m16][1] += acc[m16][nb][2] * d0 + acc[m16][nb][3] * d1;
            }
        }
#pragma unroll
        for (int m16 = 0; m16 < 2; m16++)
#pragma unroll
            for (int hh = 0; hh < 2; hh++) {
                pss[m16][hh] += __shfl_xor_sync(0xffffffffu, pss[m16][hh], 1);
                pss[m16][hh] += __shfl_xor_sync(0xffffffffu, pss[m16][hh], 2);
                psd[m16][hh] += __shfl_xor_sync(0xffffffffu, psd[m16][hh], 1);
                psd[m16][hh] += __shfl_xor_sync(0xffffffffu, psd[m16][hh], 2);
            }
        if (warpCol == 0 && (lane & 3) == 0) {
#pragma unroll
            for (int m16 = 0; m16 < 2; m16++)
#pragma unroll
                for (int hh = 0; hh < 2; hh++) {
                    int rb = warpRow * 32 + m16 * 16 + hh * 8 + (lane >> 2);
                    red_ss[rb] = pss[m16][hh];
                    red_sd[rb] = psd[m16][hh];
                }
        }
        __syncthreads();
        if (warpCol == 1 && (lane & 3) == 0) {
#pragma unroll
            for (int m16 = 0; m16 < 2; m16++)
#pragma unroll
                for (int hh = 0; hh < 2; hh++) {
                    int rb = warpRow * 32 + m16 * 16 + hh * 8 + (lane >> 2);
                    int row = rowBase + rb;
                    if (row < M) {
                        float S = red_ss[rb] + pss[m16][hh];
                        float D = red_sd[rb] + psd[m16][hh];
                        if (lmode == 1) {
                            als[row * 4 + y] = S;
                            ald[row * 4 + y] = D;
                        } else {
                            atomicAdd(&als[row], S);
                            atomicAdd(&ald[row], D);
                        }
                    }
                }
        }
    }
}

// ---------------- fused CSR aggregation, H=4, 256 ch: warp per dst (range) --------
__global__ void gat_agg256(const float* __restrict__ proj,
                           const float* __restrict__ als, const float* __restrict__ ald,
                           const float* __restrict__ bias, const float* __restrict__ res,
                           float* __restrict__ outp,
                           __nv_bfloat16* __restrict__ hi, __nv_bfloat16* __restrict__ lo,
                           int d0, int nd) {
    int w = (blockIdx.x * blockDim.x + threadIdx.x) >> 5;
    if (w >= nd) return;
    const int lane = threadIdx.x & 31;
    const int d = d0 + w;
    const float aldl = (lane < 4) ? ald[d * 4 + lane] : 0.f;

    float wt = 0.f, sden = 0.f;
    if (lane < 4) {
        wt = __expf(lrelu(als[d * 4 + lane] + aldl));
        sden = wt;
    }
    float wh = __shfl_sync(0xffffffffu, wt, lane >> 3);

    const float4* pr = (const float4*)proj;
    float4 a0, a1;
    {
        float4 p0 = pr[(size_t)d * 64 + lane * 2];
        float4 p1 = pr[(size_t)d * 64 + lane * 2 + 1];
        a0 = make_float4(wh * p0.x, wh * p0.y, wh * p0.z, wh * p0.w);
        a1 = make_float4(wh * p1.x, wh * p1.y, wh * p1.z, wh * p1.w);
    }
    const int jb = g_rowptr[d], je = g_rowptr[d + 1];
    int s = (jb < je) ? g_ssrc[jb] : 0;
    for (int j = jb; j < je; j++) {
        int sn = (j + 1 < je) ? g_ssrc[j + 1] : 0;
        float w2 = 0.f;
        if (lane < 4) {
            w2 = __expf(lrelu(als[s * 4 + lane] + aldl));
            sden += w2;
        }
        float wh2 = __shfl_sync(0xffffffffu, w2, lane >> 3);
        float4 p0 = pr[(size_t)s * 64 + lane * 2];
        float4 p1 = pr[(size_t)s * 64 + lane * 2 + 1];
        a0.x = fmaf(wh2, p0.x, a0.x); a0.y = fmaf(wh2, p0.y, a0.y);
        a0.z = fmaf(wh2, p0.z, a0.z); a0.w = fmaf(wh2, p0.w, a0.w);
        a1.x = fmaf(wh2, p1.x, a1.x); a1.y = fmaf(wh2, p1.y, a1.y);
        a1.z = fmaf(wh2, p1.z, a1.z); a1.w = fmaf(wh2, p1.w, a1.w);
        s = sn;
    }
    float inv = 1.0f / __shfl_sync(0xffffffffu, sden, lane >> 3);
    float4 b0 = ((const float4*)bias)[lane * 2];
    float4 b1 = ((const float4*)bias)[lane * 2 + 1];
    float o[8];
    o[0] = a0.x * inv + b0.x; o[1] = a0.y * inv + b0.y;
    o[2] = a0.z * inv + b0.z; o[3] = a0.w * inv + b0.w;
    o[4] = a1.x * inv + b1.x; o[5] = a1.y * inv + b1.y;
    o[6] = a1.z * inv + b1.z; o[7] = a1.w * inv + b1.w;
    if (res) {
        float4 r0 = ((const float4*)res)[(size_t)d * 64 + lane * 2];
        float4 r1 = ((const float4*)res)[(size_t)d * 64 + lane * 2 + 1];
        o[0] += r0.x; o[1] += r0.y; o[2] += r0.z; o[3] += r0.w;
        o[4] += r1.x; o[5] += r1.y; o[6] += r1.z; o[7] += r1.w;
    }
    if (outp) {
        ((float4*)outp)[(size_t)d * 64 + lane * 2] = make_float4(o[0], o[1], o[2], o[3]);
        ((float4*)outp)[(size_t)d * 64 + lane * 2 + 1] = make_float4(o[4], o[5], o[6], o[7]);
    }
    __nv_bfloat162 hv[4], lv[4];
#pragma unroll
    for (int q = 0; q < 4; q++) {
        __nv_bfloat16 h0b = __float2bfloat16(o[2 * q]);
        __nv_bfloat16 h1b = __float2bfloat16(o[2 * q + 1]);
        hv[q] = __nv_bfloat162(h0b, h1b);
        lv[q] = __nv_bfloat162(__float2bfloat16(o[2 * q] - __bfloat162float(h0b)),
                               __float2bfloat16(o[2 * q + 1] - __bfloat162float(h1b)));
    }
    *(uint4*)(hi + (size_t)d * 256 + lane * 8) = *(uint4*)hv;
    *(uint4*)(lo + (size_t)d * 256 + lane * 8) = *(uint4*)lv;
}

// ---------------- fused CSR aggregation, H=1, 128 ch (layer 2, full) --------------
__global__ void gat_agg128(const float* __restrict__ proj,
                           const float* __restrict__ als, const float* __restrict__ ald,
                           const float* __restrict__ bias, const float* __restrict__ bias2,
                           float* __restrict__ outp) {
    int w = (blockIdx.x * blockDim.x + threadIdx.x) >> 5;
    if (w >= NN) return;
    const int lane = threadIdx.x & 31;
    const int d = w;
    const float aldv = __shfl_sync(0xffffffffu, (lane == 0) ? ald[d] : 0.f, 0);

    float wt = 0.f, sden = 0.f;
    if (lane == 0) {
        wt = __expf(lrelu(als[d] + aldv));
        sden = wt;
    }
    float wh = __shfl_sync(0xffffffffu, wt, 0);
    const float4* pr = (const float4*)proj;
    float4 a0;
    {
        float4 p = pr[(size_t)d * 64 + lane];
        a0 = make_float4(wh * p.x, wh * p.y, wh * p.z, wh * p.w);
    }
    const int jb = g_rowptr[d], je = g_rowptr[d + 1];
    int s = (jb < je) ? g_ssrc[jb] : 0;
    for (int j = jb; j < je; j++) {
        int sn = (j + 1 < je) ? g_ssrc[j + 1] : 0;
        float w2 = 0.f;
        if (lane == 0) {
            w2 = __expf(lrelu(als[s] + aldv));
            sden += w2;
        }
        float wh2 = __shfl_sync(0xffffffffu, w2, 0);
        float4 p = pr[(size_t)s * 64 + lane];
        a0.x = fmaf(wh2, p.x, a0.x); a0.y = fmaf(wh2, p.y, a0.y);
        a0.z = fmaf(wh2, p.z, a0.z); a0.w = fmaf(wh2, p.w, a0.w);
        s = sn;
    }
    float inv = 1.0f / __shfl_sync(0xffffffffu, sden, 0);
    float4 b0 = ((const float4*)bias)[lane];
    float4 b2 = ((const float4*)bias2)[lane];
    float4 l0 = pr[(size_t)d * 64 + 32 + lane];
    float4 o = make_float4(a0.x * inv + b0.x + b2.x + l0.x,
                           a0.y * inv + b0.y + b2.y + l0.y,
                           a0.z * inv + b0.z + b2.z + l0.z,
                           a0.w * inv + b0.w + b2.w + l0.w);
    ((float4*)outp)[(size_t)d * 32 + lane] = o;
}

// ---------------- host orchestration ----------------
extern "C" void kernel_launch(void* const* d_in, const int* in_sizes, int n_in,
                              void* d_out, int out_size) {
    const float* x   = (const float*)d_in[0];
    const void*  ei  = d_in[1];
    const float* W0  = (const float*)d_in[2];
    const float* as0 = (const float*)d_in[3];
    const float* ad0 = (const float*)d_in[4];
    const float* b0  = (const float*)d_in[5];
    const float* W1  = (const float*)d_in[6];
    const float* as1 = (const float*)d_in[7];
    const float* ad1 = (const float*)d_in[8];
    const float* b1  = (const float*)d_in[9];
    const float* W2  = (const float*)d_in[10];
    const float* as2 = (const float*)d_in[11];
    const float* ad2 = (const float*)d_in[12];
    const float* b2  = (const float*)d_in[13];
    const float* Wl  = (const float*)d_in[14];
    const float* bl  = (const float*)d_in[15];
    float* out = (float*)d_out;
    const int E = in_sizes[1] / 2;

    float *pA, *pB, *p_h0, *alsA, *aldA, *alsB, *aldB, *als2, *ald2;
    int *p_cnt;
    __nv_bfloat16 *p_ahi, *p_alo, *p_w0hi, *p_w0lo, *p_w1hi, *p_w1lo, *p_wchi, *p_wclo;
    cudaGetSymbolAddress((void**)&pA,    g_projA);
    cudaGetSymbolAddress((void**)&pB,    g_projB);
    cudaGetSymbolAddress((void**)&p_h0,  g_h0);
    cudaGetSymbolAddress((void**)&alsA,  g_alsA);
    cudaGetSymbolAddress((void**)&aldA,  g_aldA);
    cudaGetSymbolAddress((void**)&alsB,  g_alsB);
    cudaGetSymbolAddress((void**)&aldB,  g_aldB);
    cudaGetSymbolAddress((void**)&als2,  g_als2);
    cudaGetSymbolAddress((void**)&ald2,  g_ald2);
    cudaGetSymbolAddress((void**)&p_cnt, g_cnt);
    cudaGetSymbolAddress((void**)&p_ahi, g_ahi);
    cudaGetSymbolAddress((void**)&p_alo, g_alo);
    cudaGetSymbolAddress((void**)&p_w0hi, g_w0hi);
    cudaGetSymbolAddress((void**)&p_w0lo, g_w0lo);
    cudaGetSymbolAddress((void**)&p_w1hi, g_w1hi);
    cudaGetSymbolAddress((void**)&p_w1lo, g_w1lo);
    cudaGetSymbolAddress((void**)&p_wchi, g_wchi);
    cudaGetSymbolAddress((void**)&p_wclo, g_wclo);

    constexpr int GEMM_SMEM = 2 * STG + 1024;
    cudaFuncSetAttribute((const void*)gemm_mma,
                         cudaFuncAttributeMaxDynamicSharedMemorySize, GEMM_SMEM);

    cudaStream_t sE;
    cudaStreamCreateWithFlags(&sE, cudaStreamNonBlocking);
    cudaEvent_t evFork, evCSR, evG0, evG1h1, evG1h2, evG2h2;
    cudaEventCreateWithFlags(&evFork, cudaEventDisableTiming);
    cudaEventCreateWithFlags(&evCSR,  cudaEventDisableTiming);
    cudaEventCreateWithFlags(&evG0,   cudaEventDisableTiming);
    cudaEventCreateWithFlags(&evG1h1, cudaEventDisableTiming);
    cudaEventCreateWithFlags(&evG1h2, cudaEventDisableTiming);
    cudaEventCreateWithFlags(&evG2h2, cudaEventDisableTiming);

    // layer-2 logit buffers zeroed up front (only gemm2 touches them later)
    cudaMemsetAsync(als2, 0, NN * sizeof(float));
    cudaMemsetAsync(ald2, 0, NN * sizeof(float));
    cudaEventRecord(evFork, 0);

    // ---- S1: CSR build ----
    cudaStreamWaitEvent(sE, evFork, 0);
    probe_kernel<<<1, 256, 0, sE>>>((const int*)ei, E > 4096 ? 4096 : E);
    cudaMemsetAsync(p_cnt, 0, NN * sizeof(int), sE);
    convert_hist<<<(E + 255) / 256, 256, 0, sE>>>(ei, E);
    scanA<<<NB_SCAN, 256, 0, sE>>>();
    scanB<<<1, 256, 0, sE>>>(NB_SCAN);
    scanC<<<NB_SCAN, 256, 0, sE>>>();
    scatter_kernel<<<(E + 255) / 256, 256, 0, sE>>>(E);
    cudaEventRecord(evCSR, sE);

    const int total4 = NN * KDIM / 4;
    const int AGG_B1 = (NH1 * 32 + 255) / 256;
    const int AGG_B2 = (NH2 * 32 + 255) / 256;
    const int AGG_FULL = (NN * 32 + 255) / 256;

    // ---- S0: prep + gemm0 (full) ----
    split_act<<<(total4 + 255) / 256, 256>>>(x, p_ahi, p_alo, total4);
    wsplit_all<<<768, 256>>>(W0, W1, W2, Wl);
    gemm_mma<<<dim3(BX1 + BX2, 4), 256, GEMM_SMEM>>>(p_ahi, p_alo, p_w0hi, p_w0lo,
                                                     pA, NN, HC, 1, as0, ad0, alsA, aldA, 0);
    cudaEventRecord(evG0, 0);

    // ---- layer 0 agg, split halves ----
    cudaStreamWaitEvent(0, evCSR, 0);
    gat_agg256<<<AGG_B1, 256>>>(pA, alsA, aldA, b0, nullptr, p_h0, p_ahi, p_alo, 0, NH1);
    cudaStreamWaitEvent(sE, evG0, 0);
    gat_agg256<<<AGG_B2, 256, 0, sE>>>(pA, alsA, aldA, b0, nullptr, p_h0, p_ahi, p_alo,
                                       NH1, NH2);

    // ---- layer 1 GEMM, split halves (h1 on S0 overlaps agg0_h2 on S1) ----
    gemm_mma<<<dim3(BX1, 4), 256, GEMM_SMEM>>>(p_ahi, p_alo, p_w1hi, p_w1lo,
                                               pB, NN, HC, 1, as1, ad1, alsB, aldB, 0);
    cudaEventRecord(evG1h1, 0);
    gemm_mma<<<dim3(BX2, 4), 256, GEMM_SMEM, sE>>>(p_ahi, p_alo, p_w1hi, p_w1lo,
                                                   pB, NN, HC, 1, as1, ad1, alsB, aldB, BX1);
    cudaEventRecord(evG1h2, sE);

    // ---- layer 1 agg, split halves (each needs BOTH gemm1 halves) ----
    cudaStreamWaitEvent(0, evG1h2, 0);
    gat_agg256<<<AGG_B1, 256>>>(pB, alsB, aldB, b1, p_h0, nullptr, p_ahi, p_alo, 0, NH1);
    cudaStreamWaitEvent(sE, evG1h1, 0);
    gat_agg256<<<AGG_B2, 256, 0, sE>>>(pB, alsB, aldB, b1, p_h0, nullptr, p_ahi, p_alo,
                                       NH1, NH2);

    // ---- layer 2 GEMM, split halves (h1 on S0 overlaps agg1_h2 on S1) ----
    gemm_mma<<<dim3(BX1, 4), 256, GEMM_SMEM>>>(p_ahi, p_alo, p_wchi, p_wclo,
                                               pA, NN, 256, 2, as2, ad2, als2, ald2, 0);
    gemm_mma<<<dim3(BX2, 4), 256, GEMM_SMEM, sE>>>(p_ahi, p_alo, p_wchi, p_wclo,
                                                   pA, NN, 256, 2, as2, ad2, als2, ald2, BX1);
    cudaEventRecord(evG2h2, sE);

    // ---- layer 2 agg (full) ----
    cudaStreamWaitEvent(0, evG2h2, 0);
    gat_agg128<<<AGG_FULL, 256>>>(pA, als2, ald2, b2, bl, out);

    cudaEventDestroy(evFork);
    cudaEventDestroy(evCSR);
    cudaEventDestroy(evG0);
    cudaEventDestroy(evG1h1);
    cudaEventDestroy(evG1h2);
    cudaEventDestroy(evG2h2);
    cudaStreamDestroy(sE);
}